// round 2
// baseline (speedup 1.0000x reference)
#include <cuda_runtime.h>
#include <math.h>

// ---------------------------------------------------------------------------
// DecoderLayer: B=2, S=2048, D=1024, H=16, DF=4096, DK=64
// fp32 baseline. Algebraic cuts: W2_eff head-sum; causal block-skip in QK^T
// and K-loop truncation in PV.
// ---------------------------------------------------------------------------

#define B_  2
#define S_  2048
#define D_  1024
#define H_  16
#define DF_ 4096
#define DK_ 64
#define BS_ (B_*S_)
#define SCALE_ 0.125f      /* 1/sqrt(64) */
#define EPS_   1e-5f

// -------------------------- scratch (static device) ------------------------
__device__ float g_q  [(size_t)B_*H_*S_*DK_];
__device__ float g_k  [(size_t)B_*H_*S_*DK_];
__device__ float g_v  [(size_t)B_*H_*S_*DK_];
__device__ float g_sc [(size_t)B_*H_*S_*S_];   // also reused for cross-attn P
__device__ float g_cat[(size_t)BS_*D_];
__device__ float g_tmp[(size_t)BS_*D_];
__device__ float g_a1 [(size_t)BS_*D_];
__device__ float g_at2[(size_t)BS_*D_];
__device__ float g_a2 [(size_t)BS_*D_];
__device__ float g_ffh[(size_t)BS_*DF_];
__device__ float g_w2e[(size_t)D_*D_];

// ------------------------------- GEMM ---------------------------------------
// C[z] = alpha * A[z] @ B[z](^T) (+ bias)(, relu)
// Per-z offsets: off = (z/zmod)*s1 + (z%zmod)*s2 for each of A, B, C; bias
// offset uses (z%zmod)*sBias2. All dims assumed multiples of tile sizes.
// CSKIP: skip blocks entirely above the causal diagonal (output later zeroed
//        by the softmax kernel).
// CK:    truncate the K loop at m0+BM (PV with causal-zero P).
template<int BM,int BN,int BK,int TM,int TN,int TRANSB,int RELU,int CSKIP,int CK>
__global__ __launch_bounds__(256)
void gemm_k(int M, int N, int K,
            const float* __restrict__ A,  int lda, long long sA1, long long sA2,
            const float* __restrict__ Bg, int ldb, long long sB1, long long sB2,
            float* __restrict__ C,        int ldc, long long sC1, long long sC2,
            const float* __restrict__ bias, long long sBias2,
            int zmod, float alpha)
{
    constexpr int NTX = BN / TN;
    constexpr int NTY = BM / TM;
    static_assert(NTX * NTY == 256, "thread count must be 256");

    const int tid = threadIdx.x;
    const int m0  = blockIdx.y * BM;
    const int n0  = blockIdx.x * BN;
    if (CSKIP && n0 > m0 + BM - 1) return;

    const int z  = blockIdx.z;
    const int zq = z / zmod;
    const int zr = z - zq * zmod;
    A  += zq * sA1 + zr * sA2;
    Bg += zq * sB1 + zr * sB2;
    C  += zq * sC1 + zr * sC2;
    const long long boff = (long long)zr * sBias2;

    __shared__ float As[BK][BM];
    __shared__ float Bs[BK][BN];

    const int tnb = (tid % NTX) * TN;
    const int tmb = (tid / NTX) * TM;

    float acc[TM][TN];
    #pragma unroll
    for (int i = 0; i < TM; i++)
        #pragma unroll
        for (int j = 0; j < TN; j++)
            acc[i][j] = 0.0f;

    int kend = K;
    if (CK) { int kl = m0 + BM; if (kl < kend) kend = kl; }  // multiple of BK

    for (int k0 = 0; k0 < kend; k0 += BK) {
        // ---- stage A tile (transposed into As[k][m]) ----
        constexpr int A4 = BM * BK / 4;
        #pragma unroll
        for (int la = tid; la < A4; la += 256) {
            int ar = la / (BK / 4);
            int ac = (la % (BK / 4)) * 4;
            float4 val = *(const float4*)(A + (size_t)(m0 + ar) * lda + (k0 + ac));
            As[ac + 0][ar] = val.x;
            As[ac + 1][ar] = val.y;
            As[ac + 2][ar] = val.z;
            As[ac + 3][ar] = val.w;
        }
        // ---- stage B tile ----
        if (!TRANSB) {
            constexpr int B4 = BK * BN / 4;
            #pragma unroll
            for (int lb = tid; lb < B4; lb += 256) {
                int br = lb / (BN / 4);
                int bc = (lb % (BN / 4)) * 4;
                *(float4*)&Bs[br][bc] =
                    *(const float4*)(Bg + (size_t)(k0 + br) * ldb + (n0 + bc));
            }
        } else {
            constexpr int B4 = BN * BK / 4;
            #pragma unroll
            for (int lb = tid; lb < B4; lb += 256) {
                int bn = lb / (BK / 4);
                int bc = (lb % (BK / 4)) * 4;
                float4 val = *(const float4*)(Bg + (size_t)(n0 + bn) * ldb + (k0 + bc));
                Bs[bc + 0][bn] = val.x;
                Bs[bc + 1][bn] = val.y;
                Bs[bc + 2][bn] = val.z;
                Bs[bc + 3][bn] = val.w;
            }
        }
        __syncthreads();

        #pragma unroll
        for (int kk = 0; kk < BK; kk++) {
            float ar[TM], br[TN];
            #pragma unroll
            for (int i = 0; i < TM; i++) ar[i] = As[kk][tmb + i];
            #pragma unroll
            for (int j = 0; j < TN; j++) br[j] = Bs[kk][tnb + j];
            #pragma unroll
            for (int i = 0; i < TM; i++)
                #pragma unroll
                for (int j = 0; j < TN; j++)
                    acc[i][j] = fmaf(ar[i], br[j], acc[i][j]);
        }
        __syncthreads();
    }

    #pragma unroll
    for (int i = 0; i < TM; i++) {
        const int gm = m0 + tmb + i;
        float* crow = C + (size_t)gm * ldc + n0 + tnb;
        #pragma unroll
        for (int j = 0; j < TN; j++) {
            float vv = acc[i][j] * alpha;
            if (bias) vv += bias[boff + n0 + tnb + j];
            if (RELU) vv = fmaxf(vv, 0.0f);
            crow[j] = vv;
        }
    }
}

// ------------------------------ softmax -------------------------------------
// One CTA per row (row length S_). CAUSAL: valid = (row % S_) + 1, columns
// beyond valid are written as exact 0.  Scale is pre-applied by the GEMM.
template<int CAUSAL>
__global__ __launch_bounds__(256)
void softmax_k(float* __restrict__ sc)
{
    __shared__ float buf[S_];
    __shared__ float red[256];
    const int row   = blockIdx.x;
    const int tid   = threadIdx.x;
    const int valid = CAUSAL ? (row % S_) + 1 : S_;
    float* p = sc + (size_t)row * S_;

    float mx = -3.0e38f;
    for (int t = tid; t < valid; t += 256) {
        float vv = p[t];
        buf[t] = vv;
        mx = fmaxf(mx, vv);
    }
    red[tid] = mx;
    __syncthreads();
    for (int o = 128; o > 0; o >>= 1) {
        if (tid < o) red[tid] = fmaxf(red[tid], red[tid + o]);
        __syncthreads();
    }
    mx = red[0];
    __syncthreads();

    float sum = 0.0f;
    for (int t = tid; t < valid; t += 256) {
        float e = __expf(buf[t] - mx);
        buf[t] = e;
        sum += e;
    }
    red[tid] = sum;
    __syncthreads();
    for (int o = 128; o > 0; o >>= 1) {
        if (tid < o) red[tid] += red[tid + o];
        __syncthreads();
    }
    const float inv = 1.0f / red[0];

    for (int t = tid; t < S_; t += 256)
        p[t] = (t < valid) ? buf[t] * inv : 0.0f;
}

// ------------------------- residual + LayerNorm ------------------------------
// out[row] = LN(y[row] + t[row]) * g + b   (one CTA per row of D_=1024)
__global__ __launch_bounds__(256)
void ln_k(const float* __restrict__ y, const float* __restrict__ t,
          const float* __restrict__ g, const float* __restrict__ bb,
          float* __restrict__ out)
{
    const int row = blockIdx.x;
    const int tid = threadIdx.x;
    const float* yr = y + (size_t)row * D_;
    const float* tr = t + (size_t)row * D_;

    float vloc[4];
    float s = 0.0f, s2 = 0.0f;
    #pragma unroll
    for (int i = 0; i < 4; i++) {
        int c = tid + i * 256;
        float vv = yr[c] + tr[c];
        vloc[i] = vv;
        s  += vv;
        s2 += vv * vv;
    }
    __shared__ float rs[256], rq[256];
    rs[tid] = s; rq[tid] = s2;
    __syncthreads();
    for (int o = 128; o > 0; o >>= 1) {
        if (tid < o) { rs[tid] += rs[tid + o]; rq[tid] += rq[tid + o]; }
        __syncthreads();
    }
    const float mean = rs[0] * (1.0f / D_);
    const float var  = rq[0] * (1.0f / D_) - mean * mean;
    const float inv  = rsqrtf(var + EPS_);

    float* orow = out + (size_t)row * D_;
    #pragma unroll
    for (int i = 0; i < 4; i++) {
        int c = tid + i * 256;
        orow[c] = (vloc[i] - mean) * inv * g[c] + bb[c];
    }
}

// ------------------------ W2_eff = sum_h W2[h*D+d, c] ------------------------
__global__ __launch_bounds__(256)
void w2eff_k(const float* __restrict__ W2, float* __restrict__ o)
{
    int idx = blockIdx.x * 256 + threadIdx.x;   // D_*D_ threads
    int r = idx / D_;
    int c = idx - r * D_;
    float s = 0.0f;
    #pragma unroll
    for (int h = 0; h < H_; h++)
        s += W2[((size_t)(h * D_ + r)) * D_ + c];
    o[idx] = s;
}

// ------------------------------ launcher -------------------------------------
extern "C" void kernel_launch(void* const* d_in, const int* in_sizes, int n_in,
                              void* d_out, int out_size)
{
    const float* x   = (const float*)d_in[0];
    const float* y   = (const float*)d_in[1];
    // d_in[2] = y_mask (tril causal) — implemented analytically
    const float* Wq  = (const float*)d_in[3];
    const float* bq  = (const float*)d_in[4];
    const float* Wk  = (const float*)d_in[5];
    const float* bk  = (const float*)d_in[6];
    const float* Wv  = (const float*)d_in[7];
    const float* bv  = (const float*)d_in[8];
    const float* W1  = (const float*)d_in[9];
    const float* b1  = (const float*)d_in[10];
    const float* l1g = (const float*)d_in[11];
    const float* l1b = (const float*)d_in[12];
    const float* W2  = (const float*)d_in[13];
    const float* b2  = (const float*)d_in[14];
    const float* l2g = (const float*)d_in[15];
    const float* l2b = (const float*)d_in[16];
    const float* Wf1 = (const float*)d_in[17];
    const float* bf1 = (const float*)d_in[18];
    const float* Wf2 = (const float*)d_in[19];
    const float* bf2 = (const float*)d_in[20];
    const float* l3g = (const float*)d_in[21];
    const float* l3b = (const float*)d_in[22];
    float* out = (float*)d_out;

    float *q, *k, *v, *sc, *cat, *tmp, *a1, *at2, *a2, *ffh, *w2e;
    cudaGetSymbolAddress((void**)&q,   g_q);
    cudaGetSymbolAddress((void**)&k,   g_k);
    cudaGetSymbolAddress((void**)&v,   g_v);
    cudaGetSymbolAddress((void**)&sc,  g_sc);
    cudaGetSymbolAddress((void**)&cat, g_cat);
    cudaGetSymbolAddress((void**)&tmp, g_tmp);
    cudaGetSymbolAddress((void**)&a1,  g_a1);
    cudaGetSymbolAddress((void**)&at2, g_at2);
    cudaGetSymbolAddress((void**)&a2,  g_a2);
    cudaGetSymbolAddress((void**)&ffh, g_ffh);
    cudaGetSymbolAddress((void**)&w2e, g_w2e);

    const dim3 thr(256);

    // W2_eff (independent, run first)
    w2eff_k<<<(D_ * D_) / 256, thr>>>(W2, w2e);

    // ---- QKV projections: per (b,h): [S,D] @ Wq[h][D,DK] + bias --------------
    {
        dim3 grid(DK_ / 64, S_ / 128, B_ * H_);
        long long sAD = (long long)S_ * D_;      // y per batch (z/H)
        long long sBW = (long long)D_ * DK_;     // weight per head (z%H)
        long long sC1 = (long long)H_ * S_ * DK_;
        long long sC2 = (long long)S_ * DK_;
        gemm_k<128,64,8,8,4,0,0,0,0><<<grid, thr>>>(S_, DK_, D_,
            y, D_, sAD, 0,  Wq, DK_, 0, sBW,  q, DK_, sC1, sC2,  bq, DK_, H_, 1.0f);
        gemm_k<128,64,8,8,4,0,0,0,0><<<grid, thr>>>(S_, DK_, D_,
            y, D_, sAD, 0,  Wk, DK_, 0, sBW,  k, DK_, sC1, sC2,  bk, DK_, H_, 1.0f);
        gemm_k<128,64,8,8,4,0,0,0,0><<<grid, thr>>>(S_, DK_, D_,
            y, D_, sAD, 0,  Wv, DK_, 0, sBW,  v, DK_, sC1, sC2,  bv, DK_, H_, 1.0f);
    }

    // ---- self-attn scores: sc = scale * q @ k^T  (causal block skip) ---------
    {
        dim3 grid(S_ / 128, S_ / 128, B_ * H_);
        long long sQ1 = (long long)H_ * S_ * DK_, sQ2 = (long long)S_ * DK_;
        long long sS1 = (long long)H_ * S_ * S_,  sS2 = (long long)S_ * S_;
        gemm_k<128,128,8,8,8,1,0,1,0><<<grid, thr>>>(S_, S_, DK_,
            q, DK_, sQ1, sQ2,  k, DK_, sQ1, sQ2,  sc, S_, sS1, sS2,
            nullptr, 0, H_, SCALE_);
    }
    softmax_k<1><<<B_ * H_ * S_, thr>>>(sc);

    // ---- PV -> cat (head-concat layout), K-loop truncated at diagonal -------
    {
        dim3 grid(DK_ / 64, S_ / 128, B_ * H_);
        gemm_k<128,64,8,8,4,0,0,0,1><<<grid, thr>>>(S_, DK_, S_,
            sc, S_,  (long long)H_ * S_ * S_,  (long long)S_ * S_,
            v,  DK_, (long long)H_ * S_ * DK_, (long long)S_ * DK_,
            cat, D_, (long long)S_ * D_,       (long long)DK_,
            nullptr, 0, H_, 1.0f);
    }

    // ---- a1 = LN(y + cat @ W1 + b1) -----------------------------------------
    {
        dim3 grid(D_ / 128, BS_ / 128, 1);
        gemm_k<128,128,8,8,8,0,0,0,0><<<grid, thr>>>(BS_, D_, D_,
            cat, D_, 0, 0,  W1, D_, 0, 0,  tmp, D_, 0, 0,  b1, 0, 1, 1.0f);
    }
    ln_k<<<BS_, thr>>>(y, tmp, l1g, l1b, a1);

    // ---- cross-attn scores: sc = scale * a1 @ x^T ---------------------------
    {
        dim3 grid(S_ / 128, S_ / 128, B_);
        gemm_k<128,128,8,8,8,1,0,0,0><<<grid, thr>>>(S_, S_, D_,
            a1, D_, (long long)S_ * D_, 0,
            x,  D_, (long long)S_ * D_, 0,
            sc, S_, (long long)S_ * S_, 0,
            nullptr, 0, 1, SCALE_);
    }
    softmax_k<0><<<B_ * S_, thr>>>(sc);

    // ---- attn2 = P @ x ------------------------------------------------------
    {
        dim3 grid(D_ / 128, S_ / 128, B_);
        gemm_k<128,128,8,8,8,0,0,0,0><<<grid, thr>>>(S_, D_, S_,
            sc, S_, (long long)S_ * S_, 0,
            x,  D_, (long long)S_ * D_, 0,
            at2, D_, (long long)S_ * D_, 0,
            nullptr, 0, 1, 1.0f);
    }

    // ---- a2 = LN(y + attn2 @ W2_eff + b2) -----------------------------------
    {
        dim3 grid(D_ / 128, BS_ / 128, 1);
        gemm_k<128,128,8,8,8,0,0,0,0><<<grid, thr>>>(BS_, D_, D_,
            at2, D_, 0, 0,  w2e, D_, 0, 0,  tmp, D_, 0, 0,  b2, 0, 1, 1.0f);
    }
    ln_k<<<BS_, thr>>>(y, tmp, l2g, l2b, a2);

    // ---- FFN ----------------------------------------------------------------
    {
        dim3 grid(DF_ / 128, BS_ / 128, 1);
        gemm_k<128,128,8,8,8,0,1,0,0><<<grid, thr>>>(BS_, DF_, D_,
            a2, D_, 0, 0,  Wf1, DF_, 0, 0,  ffh, DF_, 0, 0,  bf1, 0, 1, 1.0f);
    }
    {
        dim3 grid(D_ / 128, BS_ / 128, 1);
        gemm_k<128,128,8,8,8,0,0,0,0><<<grid, thr>>>(BS_, D_, DF_,
            ffh, DF_, 0, 0,  Wf2, D_, 0, 0,  tmp, D_, 0, 0,  bf2, 0, 1, 1.0f);
    }
    ln_k<<<BS_, thr>>>(y, tmp, l3g, l3b, out);
}

// round 6
// speedup vs baseline: 3.9740x; 3.9740x over previous
#include <cuda_runtime.h>
#include <cstdint>
#include <math.h>

// ---------------------------------------------------------------------------
// DecoderLayer: B=2, S=2048, D=1024, H=16, DF=4096, DK=64
// Round 5: GEMMs on mma.sync.m16n8k8.tf32 (sm_80-class PTX; runs on the
// Blackwell tensor pipe without the 'a'-gated tcgen05 ISA, which this
// toolchain's compute_103 PTX target rejects).
// All GEMM inputs are tf32-rounded at the producer; staging is cp.async.
// ---------------------------------------------------------------------------

#define B_  2
#define S_  2048
#define D_  1024
#define H_  16
#define DF_ 4096
#define DK_ 64
#define BS_ (B_*S_)
#define SCALE_ 0.125f
#define EPS_   1e-5f

// -------------------------- scratch (static device) -------------------------
__device__ float g_yr [(size_t)BS_*D_];    // y rounded (GEMM A operand)
__device__ float g_xr [(size_t)BS_*D_];    // x rounded (cross-scores B)
__device__ float g_xt [(size_t)B_*D_*S_];  // x^T rounded (attn2 B)
__device__ float g_q  [(size_t)BS_*D_];
__device__ float g_k  [(size_t)BS_*D_];
__device__ float g_vt [(size_t)B_*D_*S_];  // v^T  [b][h*64+dk][s]
__device__ float g_sc [(size_t)B_*H_*S_*S_];
__device__ float g_cat[(size_t)BS_*D_];
__device__ float g_tmp[(size_t)BS_*D_];
__device__ float g_a1 [(size_t)BS_*D_];
__device__ float g_at2[(size_t)BS_*D_];
__device__ float g_a2 [(size_t)BS_*D_];
__device__ float g_ffh[(size_t)BS_*DF_];
__device__ float g_wqt[(size_t)D_*D_];     // [h*64+dk][d] rounded
__device__ float g_wkt[(size_t)D_*D_];
__device__ float g_wvt[(size_t)D_*D_];
__device__ float g_w1t[(size_t)D_*D_];     // W1^T rounded
__device__ float g_w2e[(size_t)D_*D_];     // (sum_h W2)^T rounded
__device__ float g_wf1t[(size_t)DF_*D_];   // Wf1^T rounded
__device__ float g_wf2t[(size_t)D_*DF_];   // Wf2^T rounded

// ------------------------------ PTX helpers ---------------------------------
__device__ __forceinline__ uint32_t smem_u32(const void* p) {
    uint32_t a;
    asm("{ .reg .u64 t; cvta.to.shared.u64 t, %1; cvt.u32.u64 %0, t; }"
        : "=r"(a) : "l"(p));
    return a;
}
__device__ __forceinline__ float tf32f(float f) {
    uint32_t r;
    asm("cvt.rna.tf32.f32 %0, %1;" : "=r"(r) : "f"(f));
    return __uint_as_float(r);
}
#define CP16(dst, src) \
    asm volatile("cp.async.cg.shared.global [%0], [%1], 16;" \
                 :: "r"(dst), "l"(src))
#define CP_COMMIT() asm volatile("cp.async.commit_group;" ::: "memory")
#define LDSM4(r0,r1,r2,r3,addr) \
    asm volatile("ldmatrix.sync.aligned.m8n8.x4.shared.b16 {%0,%1,%2,%3}, [%4];" \
                 : "=r"(r0),"=r"(r1),"=r"(r2),"=r"(r3) : "r"(addr))
#define MMA8(d, a0,a1,a2,a3, b0,b1) \
    asm volatile("mma.sync.aligned.m16n8k8.row.col.f32.tf32.tf32.f32 " \
                 "{%0,%1,%2,%3},{%4,%5,%6,%7},{%8,%9},{%0,%1,%2,%3};" \
                 : "+f"(d[0]),"+f"(d[1]),"+f"(d[2]),"+f"(d[3]) \
                 : "r"(a0),"r"(a1),"r"(a2),"r"(a3),"r"(b0),"r"(b1))

// ------------------------------- tensor GEMM --------------------------------
// C[z] = alpha * A[z] @ B[z]^T (+bias)(,relu).  BM=128, BK=32, tf32 mma.sync.
// A global: [M][K] row-major (lda). B global: [N][K] row-major (ldb) — always
// k-major; all transposes are pre-materialized.
// TRC:   write C transposed (C[n][m], ldc = row stride of the [N][M] matrix)
// CSKIP: skip blocks above causal diagonal.  CK: truncate K at m0+128.
// Per-z offsets: zq=z/zmod, zr=z%zmod;  off = zq*s1 + zr*s2.
template<int BN,int TRC,int RELU,int CSKIP,int CK>
__global__ __launch_bounds__(256)
void tc_gemm(int K,
             const float* __restrict__ A,  int lda, long long sA1, long long sA2,
             const float* __restrict__ Bg, int ldb, long long sB1, long long sB2,
             float* __restrict__ C,        int ldc, long long sC1, long long sC2,
             const float* __restrict__ bias,
             int zmod, float alpha)
{
    constexpr int MW = (BN == 128) ? 2 : 4;      // warps along M
    constexpr int WM = 128 / MW;                 // 64 or 32
    constexpr int MT = WM / 16;                  // m16-tiles per warp
    constexpr int ABYTES = 128 * 128;            // 128 rows x 32 tf32
    constexpr int BBYTES = BN * 128;
    constexpr int OFF_A0 = 0, OFF_A1 = ABYTES;
    constexpr int OFF_B0 = 2 * ABYTES, OFF_B1 = 2 * ABYTES + BBYTES;

    const int m0 = blockIdx.y * 128;
    const int n0 = blockIdx.x * BN;
    if (CSKIP && n0 > m0 + 127) return;

    extern __shared__ __align__(1024) char smem[];
    const uint32_t sbase = smem_u32(smem);
    const int tid = threadIdx.x, wid = tid >> 5, lane = tid & 31;

    const int z  = blockIdx.z;
    const int zq = z / zmod;
    const int zr = z - zq * zmod;
    A  += (size_t)zq * sA1 + (size_t)zr * sA2;
    Bg += (size_t)zq * sB1 + (size_t)zr * sB2;
    C  += (size_t)zq * sC1 + (size_t)zr * sC2;

    int kend = K;
    if (CK) { int kl = m0 + 128; if (kl < kend) kend = kl; }
    const int T = kend >> 5;

    // ---------------- staging (cp.async, SW128 swizzle) ----------------
    auto stage = [&](int buf, int k0) {
        const float* Ab = A + (size_t)m0 * lda + k0;
        const uint32_t sa = sbase + (buf ? OFF_A1 : OFF_A0);
        #pragma unroll
        for (int it = 0; it < 4; it++) {
            int idx = tid + (it << 8);
            int row = idx >> 3, c4 = (idx & 7) << 2;
            uint32_t off = ((uint32_t)row << 7) + ((uint32_t)c4 << 2);
            off ^= (off >> 3) & 0x70;
            CP16(sa + off, Ab + (size_t)row * lda + c4);
        }
        const float* Bb = Bg + (size_t)n0 * ldb + k0;
        const uint32_t sb = sbase + (buf ? OFF_B1 : OFF_B0);
        #pragma unroll
        for (int it = 0; it < BN / 32; it++) {
            int idx = tid + (it << 8);
            int row = idx >> 3, c4 = (idx & 7) << 2;
            uint32_t off = ((uint32_t)row << 7) + ((uint32_t)c4 << 2);
            off ^= (off >> 3) & 0x70;
            CP16(sb + off, Bb + (size_t)row * ldb + c4);
        }
    };

    // ---------------- fragment addressing (ldmatrix) ----------------
    const int mw = wid % MW, nw = wid / MW;
    const int mbase = mw * WM, nbase = nw * 32;
    const int swz = lane & 7;
    const int caA = (lane >> 4) & 1;          // +4 k-cols for matrices 2,3
    const int caB = (lane >> 3) & 1;
    uint32_t aoffb[MT], boffb[2];
    {
        int ar0 = mbase + (lane & 7) + (((lane >> 3) & 1) << 3);
        #pragma unroll
        for (int mt = 0; mt < MT; mt++) aoffb[mt] = (uint32_t)(ar0 + mt * 16) << 7;
        int br0 = nbase + (lane & 7) + (((lane >> 4) & 1) << 3);
        #pragma unroll
        for (int p = 0; p < 2; p++) boffb[p] = (uint32_t)(br0 + p * 16) << 7;
    }

    float acc[MT][4][4];
    #pragma unroll
    for (int mt = 0; mt < MT; mt++)
        #pragma unroll
        for (int nt = 0; nt < 4; nt++)
            #pragma unroll
            for (int j = 0; j < 4; j++) acc[mt][nt][j] = 0.0f;

    // ---------------- pipelined main loop ----------------
    stage(0, 0);
    CP_COMMIT();
    for (int t = 0; t < T; t++) {
        if (t + 1 < T) {
            stage((t + 1) & 1, (t + 1) << 5);
            CP_COMMIT();
            asm volatile("cp.async.wait_group 1;" ::: "memory");
        } else {
            asm volatile("cp.async.wait_group 0;" ::: "memory");
        }
        __syncthreads();

        const uint32_t aB = sbase + ((t & 1) ? OFF_A1 : OFF_A0);
        const uint32_t bB = sbase + ((t & 1) ? OFF_B1 : OFF_B0);
        #pragma unroll
        for (int kc = 0; kc < 4; kc++) {
            const uint32_t swa = (uint32_t)(((2 * kc + caA) ^ swz) << 4);
            const uint32_t swb = (uint32_t)(((2 * kc + caB) ^ swz) << 4);
            uint32_t af[MT][4], bf[2][4];
            #pragma unroll
            for (int mt = 0; mt < MT; mt++)
                LDSM4(af[mt][0], af[mt][1], af[mt][2], af[mt][3],
                      aB + aoffb[mt] + swa);
            #pragma unroll
            for (int p = 0; p < 2; p++)
                LDSM4(bf[p][0], bf[p][1], bf[p][2], bf[p][3],
                      bB + boffb[p] + swb);
            #pragma unroll
            for (int mt = 0; mt < MT; mt++) {
                #pragma unroll
                for (int p = 0; p < 2; p++) {
                    MMA8(acc[mt][2 * p],     af[mt][0], af[mt][1], af[mt][2], af[mt][3],
                         bf[p][0], bf[p][1]);
                    MMA8(acc[mt][2 * p + 1], af[mt][0], af[mt][1], af[mt][2], af[mt][3],
                         bf[p][2], bf[p][3]);
                }
            }
        }
        __syncthreads();
    }

    // ---------------- epilogue ----------------
    const int g = lane >> 2, tg = lane & 3;
    #pragma unroll
    for (int mt = 0; mt < MT; mt++) {
        const int r0 = m0 + mbase + mt * 16 + g;
        #pragma unroll
        for (int nt = 0; nt < 4; nt++) {
            const int col = n0 + nbase + nt * 8 + tg * 2;
            float v0 = acc[mt][nt][0] * alpha, v1 = acc[mt][nt][1] * alpha;
            float v2 = acc[mt][nt][2] * alpha, v3 = acc[mt][nt][3] * alpha;
            if (bias) {
                float b0 = bias[col], b1 = bias[col + 1];
                v0 += b0; v1 += b1; v2 += b0; v3 += b1;
            }
            if (RELU) {
                v0 = fmaxf(v0, 0.f); v1 = fmaxf(v1, 0.f);
                v2 = fmaxf(v2, 0.f); v3 = fmaxf(v3, 0.f);
            }
            v0 = tf32f(v0); v1 = tf32f(v1); v2 = tf32f(v2); v3 = tf32f(v3);
            if (!TRC) {
                *(float2*)(C + (size_t)r0 * ldc + col)       = make_float2(v0, v1);
                *(float2*)(C + (size_t)(r0 + 8) * ldc + col) = make_float2(v2, v3);
            } else {
                C[(size_t)col       * ldc + r0]     = v0;
                C[(size_t)(col + 1) * ldc + r0]     = v1;
                C[(size_t)col       * ldc + r0 + 8] = v2;
                C[(size_t)(col + 1) * ldc + r0 + 8] = v3;
            }
        }
    }
}

// ------------------------------ softmax -------------------------------------
template<int CAUSAL>
__global__ __launch_bounds__(256)
void softmax_k(float* __restrict__ sc)
{
    __shared__ float buf[S_];
    __shared__ float red[256];
    const int row   = blockIdx.x;
    const int tid   = threadIdx.x;
    const int r     = row % S_;
    const int valid = CAUSAL ? r + 1 : S_;
    const int vend  = CAUSAL ? (((r >> 7) + 1) << 7) : S_;
    float* p = sc + (size_t)row * S_;

    float mx = -3.0e38f;
    for (int t = tid; t < valid; t += 256) {
        float vv = p[t];
        buf[t] = vv;
        mx = fmaxf(mx, vv);
    }
    red[tid] = mx;
    __syncthreads();
    for (int o = 128; o > 0; o >>= 1) {
        if (tid < o) red[tid] = fmaxf(red[tid], red[tid + o]);
        __syncthreads();
    }
    mx = red[0];
    __syncthreads();

    float sum = 0.0f;
    for (int t = tid; t < valid; t += 256) {
        float e = __expf(buf[t] - mx);
        buf[t] = e;
        sum += e;
    }
    red[tid] = sum;
    __syncthreads();
    for (int o = 128; o > 0; o >>= 1) {
        if (tid < o) red[tid] += red[tid + o];
        __syncthreads();
    }
    const float inv = 1.0f / red[0];

    for (int t = tid; t < vend; t += 256)
        p[t] = (t < valid) ? tf32f(buf[t] * inv) : 0.0f;
}

// ------------------------- residual + LayerNorm ------------------------------
template<int RND>
__global__ __launch_bounds__(256)
void ln_k(const float* __restrict__ y, const float* __restrict__ t,
          const float* __restrict__ g, const float* __restrict__ bb,
          float* __restrict__ out)
{
    const int row = blockIdx.x;
    const int tid = threadIdx.x;
    const float* yr = y + (size_t)row * D_;
    const float* tr = t + (size_t)row * D_;

    float vloc[4];
    float s = 0.0f, s2 = 0.0f;
    #pragma unroll
    for (int i = 0; i < 4; i++) {
        int c = tid + i * 256;
        float vv = yr[c] + tr[c];
        vloc[i] = vv;
        s  += vv;
        s2 += vv * vv;
    }
    __shared__ float rs[256], rq[256];
    rs[tid] = s; rq[tid] = s2;
    __syncthreads();
    for (int o = 128; o > 0; o >>= 1) {
        if (tid < o) { rs[tid] += rs[tid + o]; rq[tid] += rq[tid + o]; }
        __syncthreads();
    }
    const float mean = rs[0] * (1.0f / D_);
    const float var  = rq[0] * (1.0f / D_) - mean * mean;
    const float inv  = rsqrtf(var + EPS_);

    float* orow = out + (size_t)row * D_;
    #pragma unroll
    for (int i = 0; i < 4; i++) {
        int c = tid + i * 256;
        float o = (vloc[i] - mean) * inv * g[c] + bb[c];
        orow[c] = RND ? tf32f(o) : o;
    }
}

// ------------------------------ prep kernels ---------------------------------
__global__ __launch_bounds__(256)
void k_round(const float* __restrict__ in, float* __restrict__ out)
{
    int i = blockIdx.x * 256 + threadIdx.x;
    float4 v = ((const float4*)in)[i];
    v.x = tf32f(v.x); v.y = tf32f(v.y); v.z = tf32f(v.z); v.w = tf32f(v.w);
    ((float4*)out)[i] = v;
}

// out[z][c][r] = rna(in[z][r][c]); in ld = C, out ld = R
__global__ __launch_bounds__(256)
void k_tr(const float* __restrict__ in, float* __restrict__ out,
          int R, int C, long long si, long long so)
{
    __shared__ float t[32][33];
    in  += (size_t)blockIdx.z * si;
    out += (size_t)blockIdx.z * so;
    const int r0 = blockIdx.y * 32, c0 = blockIdx.x * 32;
    const int tx = threadIdx.x & 31, ty = threadIdx.x >> 5;
    #pragma unroll
    for (int j = 0; j < 4; j++)
        t[ty + j * 8][tx] = in[(size_t)(r0 + ty + j * 8) * C + c0 + tx];
    __syncthreads();
    #pragma unroll
    for (int j = 0; j < 4; j++)
        out[(size_t)(c0 + ty + j * 8) * R + r0 + tx] = tf32f(t[tx][ty + j * 8]);
}

// w2eT[c][d] = rna( sum_h W2[h*D+d][c] )
__global__ __launch_bounds__(256)
void k_w2eff(const float* __restrict__ W2, float* __restrict__ o)
{
    __shared__ float t[32][33];
    const int d0 = blockIdx.y * 32, c0 = blockIdx.x * 32;
    const int tx = threadIdx.x & 31, ty = threadIdx.x >> 5;
    float r[4] = {0.f, 0.f, 0.f, 0.f};
    for (int h = 0; h < H_; h++) {
        #pragma unroll
        for (int j = 0; j < 4; j++)
            r[j] += W2[(size_t)(h * D_ + d0 + ty + j * 8) * D_ + c0 + tx];
    }
    #pragma unroll
    for (int j = 0; j < 4; j++) t[ty + j * 8][tx] = r[j];
    __syncthreads();
    #pragma unroll
    for (int j = 0; j < 4; j++)
        o[(size_t)(c0 + ty + j * 8) * D_ + d0 + tx] = tf32f(t[tx][ty + j * 8]);
}

// ------------------------------ launcher -------------------------------------
extern "C" void kernel_launch(void* const* d_in, const int* in_sizes, int n_in,
                              void* d_out, int out_size)
{
    const float* x   = (const float*)d_in[0];
    const float* y   = (const float*)d_in[1];
    // d_in[2] = y_mask (causal tril) — analytic
    const float* Wq  = (const float*)d_in[3];
    const float* bq  = (const float*)d_in[4];
    const float* Wk  = (const float*)d_in[5];
    const float* bk  = (const float*)d_in[6];
    const float* Wv  = (const float*)d_in[7];
    const float* bv  = (const float*)d_in[8];
    const float* W1  = (const float*)d_in[9];
    const float* b1  = (const float*)d_in[10];
    const float* l1g = (const float*)d_in[11];
    const float* l1b = (const float*)d_in[12];
    const float* W2  = (const float*)d_in[13];
    const float* b2  = (const float*)d_in[14];
    const float* l2g = (const float*)d_in[15];
    const float* l2b = (const float*)d_in[16];
    const float* Wf1 = (const float*)d_in[17];
    const float* bf1 = (const float*)d_in[18];
    const float* Wf2 = (const float*)d_in[19];
    const float* bf2 = (const float*)d_in[20];
    const float* l3g = (const float*)d_in[21];
    const float* l3b = (const float*)d_in[22];
    float* out = (float*)d_out;

    float *yr, *xr, *xt, *q, *k, *vt, *sc, *cat, *tmp, *a1, *at2, *a2, *ffh;
    float *wqt, *wkt, *wvt, *w1t, *w2e, *wf1t, *wf2t;
    cudaGetSymbolAddress((void**)&yr,  g_yr);
    cudaGetSymbolAddress((void**)&xr,  g_xr);
    cudaGetSymbolAddress((void**)&xt,  g_xt);
    cudaGetSymbolAddress((void**)&q,   g_q);
    cudaGetSymbolAddress((void**)&k,   g_k);
    cudaGetSymbolAddress((void**)&vt,  g_vt);
    cudaGetSymbolAddress((void**)&sc,  g_sc);
    cudaGetSymbolAddress((void**)&cat, g_cat);
    cudaGetSymbolAddress((void**)&tmp, g_tmp);
    cudaGetSymbolAddress((void**)&a1,  g_a1);
    cudaGetSymbolAddress((void**)&at2, g_at2);
    cudaGetSymbolAddress((void**)&a2,  g_a2);
    cudaGetSymbolAddress((void**)&ffh, g_ffh);
    cudaGetSymbolAddress((void**)&wqt, g_wqt);
    cudaGetSymbolAddress((void**)&wkt, g_wkt);
    cudaGetSymbolAddress((void**)&wvt, g_wvt);
    cudaGetSymbolAddress((void**)&w1t, g_w1t);
    cudaGetSymbolAddress((void**)&w2e, g_w2e);
    cudaGetSymbolAddress((void**)&wf1t, g_wf1t);
    cudaGetSymbolAddress((void**)&wf2t, g_wf2t);

    const int SM128 = 2 * 128 * 128 + 2 * 128 * 128;   // 65536
    const int SM64  = 2 * 128 * 128 + 2 * 64 * 128;    // 49152
    cudaFuncSetAttribute(tc_gemm<128,0,0,0,0>, cudaFuncAttributeMaxDynamicSharedMemorySize, SM128);
    cudaFuncSetAttribute(tc_gemm<128,1,0,0,0>, cudaFuncAttributeMaxDynamicSharedMemorySize, SM128);
    cudaFuncSetAttribute(tc_gemm<128,0,0,1,0>, cudaFuncAttributeMaxDynamicSharedMemorySize, SM128);
    cudaFuncSetAttribute(tc_gemm<128,0,1,0,0>, cudaFuncAttributeMaxDynamicSharedMemorySize, SM128);
    cudaFuncSetAttribute(tc_gemm<64,0,0,0,1>,  cudaFuncAttributeMaxDynamicSharedMemorySize, SM64);

    const long long SD  = (long long)S_ * D_;
    const long long SS  = (long long)S_ * S_;
    const long long HSS = (long long)H_ * SS;
    const long long DS  = (long long)D_ * S_;

    // ---------------- prep: rounded / transposed copies ----------------
    k_round<<<(BS_ * D_) / 1024, 256>>>(y, yr);
    k_round<<<(BS_ * D_) / 1024, 256>>>(x, xr);
    k_tr<<<dim3(D_/32, S_/32, B_),  256>>>(x,  xt,  S_,  D_,  SD, DS);
    k_tr<<<dim3(DK_/32, D_/32, H_), 256>>>(Wq, wqt, D_,  DK_, (long long)D_*DK_, (long long)DK_*D_);
    k_tr<<<dim3(DK_/32, D_/32, H_), 256>>>(Wk, wkt, D_,  DK_, (long long)D_*DK_, (long long)DK_*D_);
    k_tr<<<dim3(DK_/32, D_/32, H_), 256>>>(Wv, wvt, D_,  DK_, (long long)D_*DK_, (long long)DK_*D_);
    k_tr<<<dim3(D_/32, D_/32, 1),   256>>>(W1, w1t, D_,  D_,  0, 0);
    k_tr<<<dim3(DF_/32, D_/32, 1),  256>>>(Wf1, wf1t, D_, DF_, 0, 0);
    k_tr<<<dim3(D_/32, DF_/32, 1),  256>>>(Wf2, wf2t, DF_, D_, 0, 0);
    k_w2eff<<<dim3(D_/32, D_/32, 1), 256>>>(W2, w2e);

    // ---------------- QKV (merged heads): [S,D] @ [1024,D]^T ----------------
    {
        dim3 g(D_ / 128, S_ / 128, B_);
        tc_gemm<128,0,0,0,0><<<g, 256, SM128>>>(D_,
            yr, D_, SD, 0,  wqt, D_, 0, 0,  q,  D_, SD, 0,  bq, 1, 1.0f);
        tc_gemm<128,0,0,0,0><<<g, 256, SM128>>>(D_,
            yr, D_, SD, 0,  wkt, D_, 0, 0,  k,  D_, SD, 0,  bk, 1, 1.0f);
        tc_gemm<128,1,0,0,0><<<g, 256, SM128>>>(D_,                 // v -> v^T
            yr, D_, SD, 0,  wvt, D_, 0, 0,  vt, S_, DS, 0,  bv, 1, 1.0f);
    }

    // ---------------- self-attn scores (causal skip) ----------------
    tc_gemm<128,0,0,1,0><<<dim3(S_/128, S_/128, B_*H_), 256, SM128>>>(DK_,
        q, D_, SD, 64,  k, D_, SD, 64,  sc, S_, HSS, SS,  nullptr, H_, SCALE_);
    softmax_k<1><<<B_ * H_ * S_, 256>>>(sc);

    // ---------------- PV -> cat [B,S,H*DK]  (K truncated) ----------------
    tc_gemm<64,0,0,0,1><<<dim3(1, S_/128, B_*H_), 256, SM64>>>(S_,
        sc, S_, HSS, SS,  vt, S_, DS, (long long)64*S_,  cat, D_, SD, 64,
        nullptr, H_, 1.0f);

    // ---------------- a1 = LN(y + cat @ W1 + b1) ----------------
    tc_gemm<128,0,0,0,0><<<dim3(D_/128, BS_/128, 1), 256, SM128>>>(D_,
        cat, D_, 0, 0,  w1t, D_, 0, 0,  tmp, D_, 0, 0,  b1, 1, 1.0f);
    ln_k<1><<<BS_, 256>>>(y, tmp, l1g, l1b, a1);

    // ---------------- cross scores + softmax ----------------
    tc_gemm<128,0,0,0,0><<<dim3(S_/128, S_/128, B_), 256, SM128>>>(D_,
        a1, D_, SD, 0,  xr, D_, SD, 0,  sc, S_, SS, 0,  nullptr, 1, SCALE_);
    softmax_k<0><<<B_ * S_, 256>>>(sc);

    // ---------------- attn2 = P @ x ----------------
    tc_gemm<128,0,0,0,0><<<dim3(D_/128, S_/128, B_), 256, SM128>>>(S_,
        sc, S_, SS, 0,  xt, S_, DS, 0,  at2, D_, SD, 0,  nullptr, 1, 1.0f);

    // ---------------- a2 = LN(y + attn2 @ W2_eff + b2) ----------------
    tc_gemm<128,0,0,0,0><<<dim3(D_/128, BS_/128, 1), 256, SM128>>>(D_,
        at2, D_, 0, 0,  w2e, D_, 0, 0,  tmp, D_, 0, 0,  b2, 1, 1.0f);
    ln_k<1><<<BS_, 256>>>(y, tmp, l2g, l2b, a2);

    // ---------------- FFN ----------------
    tc_gemm<128,0,1,0,0><<<dim3(DF_/128, BS_/128, 1), 256, SM128>>>(D_,
        a2, D_, 0, 0,  wf1t, D_, 0, 0,  ffh, DF_, 0, 0,  bf1, 1, 1.0f);
    tc_gemm<128,0,0,0,0><<<dim3(D_/128, BS_/128, 1), 256, SM128>>>(DF_,
        ffh, DF_, 0, 0,  wf2t, DF_, 0, 0,  tmp, D_, 0, 0,  bf2, 1, 1.0f);
    ln_k<0><<<BS_, 256>>>(y, tmp, l3g, l3b, out);
}

// round 10
// speedup vs baseline: 4.6336x; 1.1660x over previous
#include <cuda_runtime.h>
#include <cstdint>
#include <math.h>

// ---------------------------------------------------------------------------
// DecoderLayer: B=2, S=2048, D=1024, H=16, DF=4096, DK=64
// Round 7: Round-5 mma.sync tf32 GEMMs + fused flash self-attention
// (QK^T + causal online-softmax + PV in one kernel).
// ---------------------------------------------------------------------------

#define B_  2
#define S_  2048
#define D_  1024
#define H_  16
#define DF_ 4096
#define DK_ 64
#define BS_ (B_*S_)
#define SCALE_ 0.125f
#define EPS_   1e-5f

// -------------------------- scratch (static device) -------------------------
__device__ float g_yr [(size_t)BS_*D_];
__device__ float g_xr [(size_t)BS_*D_];
__device__ float g_xt [(size_t)B_*D_*S_];
__device__ float g_q  [(size_t)BS_*D_];
__device__ float g_k  [(size_t)BS_*D_];
__device__ float g_vt [(size_t)B_*D_*S_];   // v^T [b][h*64+dk][s]
__device__ float g_sc [(size_t)B_*S_*S_];   // cross-attn scores only
__device__ float g_cat[(size_t)BS_*D_];
__device__ float g_tmp[(size_t)BS_*D_];
__device__ float g_a1 [(size_t)BS_*D_];
__device__ float g_at2[(size_t)BS_*D_];
__device__ float g_a2 [(size_t)BS_*D_];
__device__ float g_ffh[(size_t)BS_*DF_];
__device__ float g_wqt[(size_t)D_*D_];
__device__ float g_wkt[(size_t)D_*D_];
__device__ float g_wvt[(size_t)D_*D_];
__device__ float g_w1t[(size_t)D_*D_];
__device__ float g_w2e[(size_t)D_*D_];
__device__ float g_wf1t[(size_t)DF_*D_];
__device__ float g_wf2t[(size_t)D_*DF_];

// ------------------------------ PTX helpers ---------------------------------
__device__ __forceinline__ uint32_t smem_u32(const void* p) {
    uint32_t a;
    asm("{ .reg .u64 t; cvta.to.shared.u64 t, %1; cvt.u32.u64 %0, t; }"
        : "=r"(a) : "l"(p));
    return a;
}
__device__ __forceinline__ float tf32f(float f) {
    uint32_t r;
    asm("cvt.rna.tf32.f32 %0, %1;" : "=r"(r) : "f"(f));
    return __uint_as_float(r);
}
#define CP16(dst, src) \
    asm volatile("cp.async.cg.shared.global [%0], [%1], 16;" \
                 :: "r"(dst), "l"(src))
#define CP_COMMIT() asm volatile("cp.async.commit_group;" ::: "memory")
#define CP_WAIT0()  asm volatile("cp.async.wait_group 0;" ::: "memory")
#define LDSM4(r0,r1,r2,r3,addr) \
    asm volatile("ldmatrix.sync.aligned.m8n8.x4.shared.b16 {%0,%1,%2,%3}, [%4];" \
                 : "=r"(r0),"=r"(r1),"=r"(r2),"=r"(r3) : "r"(addr))
#define MMA8(d, a0,a1,a2,a3, b0,b1) \
    asm volatile("mma.sync.aligned.m16n8k8.row.col.f32.tf32.tf32.f32 " \
                 "{%0,%1,%2,%3},{%4,%5,%6,%7},{%8,%9},{%0,%1,%2,%3};" \
                 : "+f"(d[0]),"+f"(d[1]),"+f"(d[2]),"+f"(d[3]) \
                 : "r"(a0),"r"(a1),"r"(a2),"r"(a3),"r"(b0),"r"(b1))

// ------------------------------- tensor GEMM --------------------------------
// (unchanged from Round 5 — proven correct)
template<int BN,int TRC,int RELU,int CSKIP,int CK>
__global__ __launch_bounds__(256)
void tc_gemm(int K,
             const float* __restrict__ A,  int lda, long long sA1, long long sA2,
             const float* __restrict__ Bg, int ldb, long long sB1, long long sB2,
             float* __restrict__ C,        int ldc, long long sC1, long long sC2,
             const float* __restrict__ bias,
             int zmod, float alpha)
{
    constexpr int MW = (BN == 128) ? 2 : 4;
    constexpr int WM = 128 / MW;
    constexpr int MT = WM / 16;
    constexpr int ABYTES = 128 * 128;
    constexpr int BBYTES = BN * 128;
    constexpr int OFF_A0 = 0, OFF_A1 = ABYTES;
    constexpr int OFF_B0 = 2 * ABYTES, OFF_B1 = 2 * ABYTES + BBYTES;

    const int m0 = blockIdx.y * 128;
    const int n0 = blockIdx.x * BN;
    if (CSKIP && n0 > m0 + 127) return;

    extern __shared__ __align__(1024) char smem[];
    const uint32_t sbase = smem_u32(smem);
    const int tid = threadIdx.x, wid = tid >> 5, lane = tid & 31;

    const int z  = blockIdx.z;
    const int zq = z / zmod;
    const int zr = z - zq * zmod;
    A  += (size_t)zq * sA1 + (size_t)zr * sA2;
    Bg += (size_t)zq * sB1 + (size_t)zr * sB2;
    C  += (size_t)zq * sC1 + (size_t)zr * sC2;

    int kend = K;
    if (CK) { int kl = m0 + 128; if (kl < kend) kend = kl; }
    const int T = kend >> 5;

    auto stage = [&](int buf, int k0) {
        const float* Ab = A + (size_t)m0 * lda + k0;
        const uint32_t sa = sbase + (buf ? OFF_A1 : OFF_A0);
        #pragma unroll
        for (int it = 0; it < 4; it++) {
            int idx = tid + (it << 8);
            int row = idx >> 3, c4 = (idx & 7) << 2;
            uint32_t off = ((uint32_t)row << 7) + ((uint32_t)c4 << 2);
            off ^= (off >> 3) & 0x70;
            CP16(sa + off, Ab + (size_t)row * lda + c4);
        }
        const float* Bb = Bg + (size_t)n0 * ldb + k0;
        const uint32_t sb = sbase + (buf ? OFF_B1 : OFF_B0);
        #pragma unroll
        for (int it = 0; it < BN / 32; it++) {
            int idx = tid + (it << 8);
            int row = idx >> 3, c4 = (idx & 7) << 2;
            uint32_t off = ((uint32_t)row << 7) + ((uint32_t)c4 << 2);
            off ^= (off >> 3) & 0x70;
            CP16(sb + off, Bb + (size_t)row * ldb + c4);
        }
    };

    const int mw = wid % MW, nw = wid / MW;
    const int mbase = mw * WM, nbase = nw * 32;
    const int swz = lane & 7;
    const int caA = (lane >> 4) & 1;
    const int caB = (lane >> 3) & 1;
    uint32_t aoffb[MT], boffb[2];
    {
        int ar0 = mbase + (lane & 7) + (((lane >> 3) & 1) << 3);
        #pragma unroll
        for (int mt = 0; mt < MT; mt++) aoffb[mt] = (uint32_t)(ar0 + mt * 16) << 7;
        int br0 = nbase + (lane & 7) + (((lane >> 4) & 1) << 3);
        #pragma unroll
        for (int p = 0; p < 2; p++) boffb[p] = (uint32_t)(br0 + p * 16) << 7;
    }

    float acc[MT][4][4];
    #pragma unroll
    for (int mt = 0; mt < MT; mt++)
        #pragma unroll
        for (int nt = 0; nt < 4; nt++)
            #pragma unroll
            for (int j = 0; j < 4; j++) acc[mt][nt][j] = 0.0f;

    stage(0, 0);
    CP_COMMIT();
    for (int t = 0; t < T; t++) {
        if (t + 1 < T) {
            stage((t + 1) & 1, (t + 1) << 5);
            CP_COMMIT();
            asm volatile("cp.async.wait_group 1;" ::: "memory");
        } else {
            CP_WAIT0();
        }
        __syncthreads();

        const uint32_t aB = sbase + ((t & 1) ? OFF_A1 : OFF_A0);
        const uint32_t bB = sbase + ((t & 1) ? OFF_B1 : OFF_B0);
        #pragma unroll
        for (int kc = 0; kc < 4; kc++) {
            const uint32_t swa = (uint32_t)(((2 * kc + caA) ^ swz) << 4);
            const uint32_t swb = (uint32_t)(((2 * kc + caB) ^ swz) << 4);
            uint32_t af[MT][4], bf[2][4];
            #pragma unroll
            for (int mt = 0; mt < MT; mt++)
                LDSM4(af[mt][0], af[mt][1], af[mt][2], af[mt][3],
                      aB + aoffb[mt] + swa);
            #pragma unroll
            for (int p = 0; p < 2; p++)
                LDSM4(bf[p][0], bf[p][1], bf[p][2], bf[p][3],
                      bB + boffb[p] + swb);
            #pragma unroll
            for (int mt = 0; mt < MT; mt++) {
                #pragma unroll
                for (int p = 0; p < 2; p++) {
                    MMA8(acc[mt][2 * p],     af[mt][0], af[mt][1], af[mt][2], af[mt][3],
                         bf[p][0], bf[p][1]);
                    MMA8(acc[mt][2 * p + 1], af[mt][0], af[mt][1], af[mt][2], af[mt][3],
                         bf[p][2], bf[p][3]);
                }
            }
        }
        __syncthreads();
    }

    const int g = lane >> 2, tg = lane & 3;
    #pragma unroll
    for (int mt = 0; mt < MT; mt++) {
        const int r0 = m0 + mbase + mt * 16 + g;
        #pragma unroll
        for (int nt = 0; nt < 4; nt++) {
            const int col = n0 + nbase + nt * 8 + tg * 2;
            float v0 = acc[mt][nt][0] * alpha, v1 = acc[mt][nt][1] * alpha;
            float v2 = acc[mt][nt][2] * alpha, v3 = acc[mt][nt][3] * alpha;
            if (bias) {
                float b0 = bias[col], b1 = bias[col + 1];
                v0 += b0; v1 += b1; v2 += b0; v3 += b1;
            }
            if (RELU) {
                v0 = fmaxf(v0, 0.f); v1 = fmaxf(v1, 0.f);
                v2 = fmaxf(v2, 0.f); v3 = fmaxf(v3, 0.f);
            }
            v0 = tf32f(v0); v1 = tf32f(v1); v2 = tf32f(v2); v3 = tf32f(v3);
            if (!TRC) {
                *(float2*)(C + (size_t)r0 * ldc + col)       = make_float2(v0, v1);
                *(float2*)(C + (size_t)(r0 + 8) * ldc + col) = make_float2(v2, v3);
            } else {
                C[(size_t)col       * ldc + r0]     = v0;
                C[(size_t)(col + 1) * ldc + r0]     = v1;
                C[(size_t)col       * ldc + r0 + 8] = v2;
                C[(size_t)(col + 1) * ldc + r0 + 8] = v3;
            }
        }
    }
}

// --------------------------- flash self-attention ----------------------------
// Per CTA: 128 q-rows of one (b,h). Iterates key tiles of 128 up to the
// causal diagonal. 8 warps: 4 along M (32 rows each) x 2 along N.
// S-phase: warp 32x64 of the 128x128 score tile. PV-phase: warp 32x32 of
// the 128x64 output tile. P round-trips through smem (tf32-rounded).
__global__ __launch_bounds__(256)
void flash_k(const float* __restrict__ qg, const float* __restrict__ kg,
             const float* __restrict__ vtg, float* __restrict__ catg)
{
    constexpr int OFF_Q = 0;                 // 2 x [128][32] = 32KB
    constexpr int OFF_K = 32768;             // 2 x [128][32] = 32KB
    constexpr int OFF_V = 65536;             // 4 x [64][32]  = 32KB
    constexpr int OFF_P = 98304;             // 4 x [128][32] = 64KB
    constexpr int OFF_PM = 163840;           // [2][128] f32
    constexpr int OFF_PL = 164864;           // [2][128] f32

    const int qb = blockIdx.x, h = blockIdx.y, b = blockIdx.z;
    extern __shared__ __align__(1024) char smem[];
    const uint32_t sbase = smem_u32(smem);
    const int tid = threadIdx.x, wid = tid >> 5, lane = tid & 31;
    const int mw = wid & 3, nw = wid >> 2;
    const int mbase = mw * 32;
    const int nbS = nw * 64;
    const int nbV = nw * 32;
    const int g = lane >> 2, tg = lane & 3;
    const int swz = lane & 7;
    const int caA = (lane >> 4) & 1, caB = (lane >> 3) & 1;

    const float* Qs = qg  + (size_t)b * ((size_t)S_ * D_) + (size_t)(qb * 128) * D_ + h * 64;
    const float* Ks = kg  + (size_t)b * ((size_t)S_ * D_) + h * 64;
    const float* Vs = vtg + (size_t)b * ((size_t)D_ * S_) + (size_t)(h * 64) * S_;

    uint32_t aoffb[2], boffS[4], boffV[2];
    {
        int ar0 = mbase + (lane & 7) + (((lane >> 3) & 1) << 3);
        aoffb[0] = (uint32_t)ar0 << 7;
        aoffb[1] = (uint32_t)(ar0 + 16) << 7;
        int br0 = nbS + (lane & 7) + (((lane >> 4) & 1) << 3);
        #pragma unroll
        for (int p = 0; p < 4; p++) boffS[p] = (uint32_t)(br0 + p * 16) << 7;
        int bv0 = nbV + (lane & 7) + (((lane >> 4) & 1) << 3);
        boffV[0] = (uint32_t)bv0 << 7;
        boffV[1] = (uint32_t)(bv0 + 16) << 7;
    }

    // ---- stage Q (resident) ----
    #pragma unroll
    for (int c = 0; c < 2; c++)
        #pragma unroll
        for (int it = 0; it < 4; it++) {
            int idx = tid + (it << 8);
            int row = idx >> 3, c4 = (idx & 7) << 2;
            uint32_t off = ((uint32_t)row << 7) + ((uint32_t)c4 << 2);
            off ^= (off >> 3) & 0x70;
            CP16(sbase + OFF_Q + c * 16384 + off, Qs + (size_t)row * D_ + c * 32 + c4);
        }
    CP_COMMIT();

    float oacc[2][4][4];
    #pragma unroll
    for (int mt = 0; mt < 2; mt++)
        #pragma unroll
        for (int nt = 0; nt < 4; nt++)
            #pragma unroll
            for (int j = 0; j < 4; j++) oacc[mt][nt][j] = 0.0f;
    float m_run[2][2] = {{-1e30f, -1e30f}, {-1e30f, -1e30f}};
    float l_run[2][2] = {{0.f, 0.f}, {0.f, 0.f}};
    float* pm = (float*)(smem + OFF_PM);
    float* pl = (float*)(smem + OFF_PL);

    for (int kb = 0; kb <= qb; kb++) {
        // ---- stage K, V tiles ----
        #pragma unroll
        for (int c = 0; c < 2; c++)
            #pragma unroll
            for (int it = 0; it < 4; it++) {
                int idx = tid + (it << 8);
                int row = idx >> 3, c4 = (idx & 7) << 2;
                uint32_t off = ((uint32_t)row << 7) + ((uint32_t)c4 << 2);
                off ^= (off >> 3) & 0x70;
                CP16(sbase + OFF_K + c * 16384 + off,
                     Ks + (size_t)(kb * 128 + row) * D_ + c * 32 + c4);
            }
        #pragma unroll
        for (int c = 0; c < 4; c++)
            #pragma unroll
            for (int it = 0; it < 2; it++) {
                int idx = tid + (it << 8);
                int row = idx >> 3, c4 = (idx & 7) << 2;
                uint32_t off = ((uint32_t)row << 7) + ((uint32_t)c4 << 2);
                off ^= (off >> 3) & 0x70;
                CP16(sbase + OFF_V + c * 8192 + off,
                     Vs + (size_t)row * S_ + kb * 128 + c * 32 + c4);
            }
        CP_COMMIT();
        CP_WAIT0();
        __syncthreads();

        // ---- S = Q @ K^T (warp 32x64) ----
        float sacc[2][8][4];
        #pragma unroll
        for (int mt = 0; mt < 2; mt++)
            #pragma unroll
            for (int nt = 0; nt < 8; nt++)
                #pragma unroll
                for (int j = 0; j < 4; j++) sacc[mt][nt][j] = 0.0f;
        #pragma unroll
        for (int ch = 0; ch < 2; ch++) {
            const uint32_t aB = sbase + OFF_Q + ch * 16384;
            const uint32_t bB = sbase + OFF_K + ch * 16384;
            #pragma unroll
            for (int kc = 0; kc < 4; kc++) {
                const uint32_t swa = (uint32_t)(((2 * kc + caA) ^ swz) << 4);
                const uint32_t swb = (uint32_t)(((2 * kc + caB) ^ swz) << 4);
                uint32_t af[2][4], bf[4][4];
                #pragma unroll
                for (int mt = 0; mt < 2; mt++)
                    LDSM4(af[mt][0], af[mt][1], af[mt][2], af[mt][3],
                          aB + aoffb[mt] + swa);
                #pragma unroll
                for (int p = 0; p < 4; p++)
                    LDSM4(bf[p][0], bf[p][1], bf[p][2], bf[p][3],
                          bB + boffS[p] + swb);
                #pragma unroll
                for (int mt = 0; mt < 2; mt++)
                    #pragma unroll
                    for (int p = 0; p < 4; p++) {
                        MMA8(sacc[mt][2 * p],     af[mt][0], af[mt][1], af[mt][2], af[mt][3],
                             bf[p][0], bf[p][1]);
                        MMA8(sacc[mt][2 * p + 1], af[mt][0], af[mt][1], af[mt][2], af[mt][3],
                             bf[p][2], bf[p][3]);
                    }
            }
        }

        // ---- scale + causal mask + row max ----
        const bool diag = (kb == qb);
        float tmx[2][2] = {{-1e30f, -1e30f}, {-1e30f, -1e30f}};
        #pragma unroll
        for (int mt = 0; mt < 2; mt++)
            #pragma unroll
            for (int nt = 0; nt < 8; nt++)
                #pragma unroll
                for (int j = 0; j < 4; j++) {
                    float v = sacc[mt][nt][j] * SCALE_;
                    if (diag) {
                        int cl = nbS + nt * 8 + tg * 2 + (j & 1);
                        int rl = mbase + mt * 16 + g + ((j & 2) << 2);
                        if (cl > rl) v = -1e30f;
                    }
                    sacc[mt][nt][j] = v;
                    tmx[mt][j >> 1] = fmaxf(tmx[mt][j >> 1], v);
                }
        #pragma unroll
        for (int mt = 0; mt < 2; mt++)
            #pragma unroll
            for (int hh = 0; hh < 2; hh++) {
                float t = tmx[mt][hh];
                t = fmaxf(t, __shfl_xor_sync(0xffffffffu, t, 1));
                t = fmaxf(t, __shfl_xor_sync(0xffffffffu, t, 2));
                tmx[mt][hh] = t;
                if (tg == 0)
                    pm[nw * 128 + mbase + mt * 16 + hh * 8 + g] = t;
            }
        __syncthreads();

        float cf[2][2], mnew[2][2];
        #pragma unroll
        for (int mt = 0; mt < 2; mt++)
            #pragma unroll
            for (int hh = 0; hh < 2; hh++) {
                int r = mbase + mt * 16 + hh * 8 + g;
                float tm = fmaxf(pm[r], pm[128 + r]);
                float mn = fmaxf(m_run[mt][hh], tm);
                cf[mt][hh] = __expf(m_run[mt][hh] - mn);
                m_run[mt][hh] = mn;
                mnew[mt][hh] = mn;
            }

        // ---- exp + P store (tf32) + partial sums ----
        float ts[2][2] = {{0.f, 0.f}, {0.f, 0.f}};
        #pragma unroll
        for (int mt = 0; mt < 2; mt++) {
            const int r0 = mbase + mt * 16 + g;
            #pragma unroll
            for (int nt = 0; nt < 8; nt++) {
                const int col = nbS + nt * 8 + tg * 2;
                float p0 = __expf(sacc[mt][nt][0] - mnew[mt][0]);
                float p1 = __expf(sacc[mt][nt][1] - mnew[mt][0]);
                float p2 = __expf(sacc[mt][nt][2] - mnew[mt][1]);
                float p3 = __expf(sacc[mt][nt][3] - mnew[mt][1]);
                ts[mt][0] += p0 + p1;
                ts[mt][1] += p2 + p3;
                uint32_t off0 = (uint32_t)(col >> 5) * 16384 +
                                ((uint32_t)r0 << 7) + ((uint32_t)(col & 31) << 2);
                off0 ^= (off0 >> 3) & 0x70;
                *(float2*)(smem + OFF_P + off0) = make_float2(tf32f(p0), tf32f(p1));
                uint32_t off1 = (uint32_t)(col >> 5) * 16384 +
                                ((uint32_t)(r0 + 8) << 7) + ((uint32_t)(col & 31) << 2);
                off1 ^= (off1 >> 3) & 0x70;
                *(float2*)(smem + OFF_P + off1) = make_float2(tf32f(p2), tf32f(p3));
            }
        }
        #pragma unroll
        for (int mt = 0; mt < 2; mt++)
            #pragma unroll
            for (int hh = 0; hh < 2; hh++) {
                float t = ts[mt][hh];
                t += __shfl_xor_sync(0xffffffffu, t, 1);
                t += __shfl_xor_sync(0xffffffffu, t, 2);
                if (tg == 0)
                    pl[nw * 128 + mbase + mt * 16 + hh * 8 + g] = t;
            }
        __syncthreads();

        #pragma unroll
        for (int mt = 0; mt < 2; mt++)
            #pragma unroll
            for (int hh = 0; hh < 2; hh++) {
                int r = mbase + mt * 16 + hh * 8 + g;
                l_run[mt][hh] = l_run[mt][hh] * cf[mt][hh] + pl[r] + pl[128 + r];
            }
        #pragma unroll
        for (int mt = 0; mt < 2; mt++)
            #pragma unroll
            for (int nt = 0; nt < 4; nt++)
                #pragma unroll
                for (int j = 0; j < 4; j++)
                    oacc[mt][nt][j] *= cf[mt][j >> 1];

        // ---- O += P @ V (warp 32x32) ----
        #pragma unroll
        for (int ch = 0; ch < 4; ch++) {
            const uint32_t aB = sbase + OFF_P + ch * 16384;
            const uint32_t bB = sbase + OFF_V + ch * 8192;
            #pragma unroll
            for (int kc = 0; kc < 4; kc++) {
                const uint32_t swa = (uint32_t)(((2 * kc + caA) ^ swz) << 4);
                const uint32_t swb = (uint32_t)(((2 * kc + caB) ^ swz) << 4);
                uint32_t af[2][4], bf[2][4];
                #pragma unroll
                for (int mt = 0; mt < 2; mt++)
                    LDSM4(af[mt][0], af[mt][1], af[mt][2], af[mt][3],
                          aB + aoffb[mt] + swa);
                #pragma unroll
                for (int p = 0; p < 2; p++)
                    LDSM4(bf[p][0], bf[p][1], bf[p][2], bf[p][3],
                          bB + boffV[p] + swb);
                #pragma unroll
                for (int mt = 0; mt < 2; mt++)
                    #pragma unroll
                    for (int p = 0; p < 2; p++) {
                        MMA8(oacc[mt][2 * p],     af[mt][0], af[mt][1], af[mt][2], af[mt][3],
                             bf[p][0], bf[p][1]);
                        MMA8(oacc[mt][2 * p + 1], af[mt][0], af[mt][1], af[mt][2], af[mt][3],
                             bf[p][2], bf[p][3]);
                    }
            }
        }
        __syncthreads();   // protect K/V/P buffers before next tile
    }

    // ---- epilogue: O / l -> cat (tf32-rounded) ----
    float* dst = catg + (size_t)b * ((size_t)S_ * D_) + (size_t)(qb * 128) * D_ + h * 64;
    #pragma unroll
    for (int mt = 0; mt < 2; mt++) {
        const int r0 = mbase + mt * 16 + g;
        const float i0 = 1.0f / l_run[mt][0];
        const float i1 = 1.0f / l_run[mt][1];
        #pragma unroll
        for (int nt = 0; nt < 4; nt++) {
            const int col = nbV + nt * 8 + tg * 2;
            *(float2*)(dst + (size_t)r0 * D_ + col) =
                make_float2(tf32f(oacc[mt][nt][0] * i0), tf32f(oacc[mt][nt][1] * i0));
            *(float2*)(dst + (size_t)(r0 + 8) * D_ + col) =
                make_float2(tf32f(oacc[mt][nt][2] * i1), tf32f(oacc[mt][nt][3] * i1));
        }
    }
}

// ------------------------------ softmax (cross) ------------------------------
__global__ __launch_bounds__(256)
void softmax_k(float* __restrict__ sc)
{
    __shared__ float buf[S_];
    __shared__ float red[256];
    const int row = blockIdx.x;
    const int tid = threadIdx.x;
    float* p = sc + (size_t)row * S_;

    float mx = -3.0e38f;
    for (int t = tid; t < S_; t += 256) {
        float vv = p[t];
        buf[t] = vv;
        mx = fmaxf(mx, vv);
    }
    red[tid] = mx;
    __syncthreads();
    for (int o = 128; o > 0; o >>= 1) {
        if (tid < o) red[tid] = fmaxf(red[tid], red[tid + o]);
        __syncthreads();
    }
    mx = red[0];
    __syncthreads();

    float sum = 0.0f;
    for (int t = tid; t < S_; t += 256) {
        float e = __expf(buf[t] - mx);
        buf[t] = e;
        sum += e;
    }
    red[tid] = sum;
    __syncthreads();
    for (int o = 128; o > 0; o >>= 1) {
        if (tid < o) red[tid] += red[tid + o];
        __syncthreads();
    }
    const float inv = 1.0f / red[0];

    for (int t = tid; t < S_; t += 256)
        p[t] = tf32f(buf[t] * inv);
}

// ------------------------- residual + LayerNorm ------------------------------
template<int RND>
__global__ __launch_bounds__(256)
void ln_k(const float* __restrict__ y, const float* __restrict__ t,
          const float* __restrict__ g, const float* __restrict__ bb,
          float* __restrict__ out)
{
    const int row = blockIdx.x;
    const int tid = threadIdx.x;
    const float* yr = y + (size_t)row * D_;
    const float* tr = t + (size_t)row * D_;

    float vloc[4];
    float s = 0.0f, s2 = 0.0f;
    #pragma unroll
    for (int i = 0; i < 4; i++) {
        int c = tid + i * 256;
        float vv = yr[c] + tr[c];
        vloc[i] = vv;
        s  += vv;
        s2 += vv * vv;
    }
    __shared__ float rs[256], rq[256];
    rs[tid] = s; rq[tid] = s2;
    __syncthreads();
    for (int o = 128; o > 0; o >>= 1) {
        if (tid < o) { rs[tid] += rs[tid + o]; rq[tid] += rq[tid + o]; }
        __syncthreads();
    }
    const float mean = rs[0] * (1.0f / D_);
    const float var  = rq[0] * (1.0f / D_) - mean * mean;
    const float inv  = rsqrtf(var + EPS_);

    float* orow = out + (size_t)row * D_;
    #pragma unroll
    for (int i = 0; i < 4; i++) {
        int c = tid + i * 256;
        float o = (vloc[i] - mean) * inv * g[c] + bb[c];
        orow[c] = RND ? tf32f(o) : o;
    }
}

// ------------------------------ prep kernels ---------------------------------
__global__ __launch_bounds__(256)
void k_round(const float* __restrict__ in, float* __restrict__ out)
{
    int i = blockIdx.x * 256 + threadIdx.x;
    float4 v = ((const float4*)in)[i];
    v.x = tf32f(v.x); v.y = tf32f(v.y); v.z = tf32f(v.z); v.w = tf32f(v.w);
    ((float4*)out)[i] = v;
}

__global__ __launch_bounds__(256)
void k_tr(const float* __restrict__ in, float* __restrict__ out,
          int R, int C, long long si, long long so)
{
    __shared__ float t[32][33];
    in  += (size_t)blockIdx.z * si;
    out += (size_t)blockIdx.z * so;
    const int r0 = blockIdx.y * 32, c0 = blockIdx.x * 32;
    const int tx = threadIdx.x & 31, ty = threadIdx.x >> 5;
    #pragma unroll
    for (int j = 0; j < 4; j++)
        t[ty + j * 8][tx] = in[(size_t)(r0 + ty + j * 8) * C + c0 + tx];
    __syncthreads();
    #pragma unroll
    for (int j = 0; j < 4; j++)
        out[(size_t)(c0 + ty + j * 8) * R + r0 + tx] = tf32f(t[tx][ty + j * 8]);
}

__global__ __launch_bounds__(256)
void k_w2eff(const float* __restrict__ W2, float* __restrict__ o)
{
    __shared__ float t[32][33];
    const int d0 = blockIdx.y * 32, c0 = blockIdx.x * 32;
    const int tx = threadIdx.x & 31, ty = threadIdx.x >> 5;
    float r[4] = {0.f, 0.f, 0.f, 0.f};
    for (int h = 0; h < H_; h++) {
        #pragma unroll
        for (int j = 0; j < 4; j++)
            r[j] += W2[(size_t)(h * D_ + d0 + ty + j * 8) * D_ + c0 + tx];
    }
    #pragma unroll
    for (int j = 0; j < 4; j++) t[ty + j * 8][tx] = r[j];
    __syncthreads();
    #pragma unroll
    for (int j = 0; j < 4; j++)
        o[(size_t)(c0 + ty + j * 8) * D_ + d0 + tx] = tf32f(t[tx][ty + j * 8]);
}

// ------------------------------ launcher -------------------------------------
extern "C" void kernel_launch(void* const* d_in, const int* in_sizes, int n_in,
                              void* d_out, int out_size)
{
    const float* x   = (const float*)d_in[0];
    const float* y   = (const float*)d_in[1];
    // d_in[2] = y_mask (causal tril) — analytic
    const float* Wq  = (const float*)d_in[3];
    const float* bq  = (const float*)d_in[4];
    const float* Wk  = (const float*)d_in[5];
    const float* bk  = (const float*)d_in[6];
    const float* Wv  = (const float*)d_in[7];
    const float* bv  = (const float*)d_in[8];
    const float* W1  = (const float*)d_in[9];
    const float* b1  = (const float*)d_in[10];
    const float* l1g = (const float*)d_in[11];
    const float* l1b = (const float*)d_in[12];
    const float* W2  = (const float*)d_in[13];
    const float* b2  = (const float*)d_in[14];
    const float* l2g = (const float*)d_in[15];
    const float* l2b = (const float*)d_in[16];
    const float* Wf1 = (const float*)d_in[17];
    const float* bf1 = (const float*)d_in[18];
    const float* Wf2 = (const float*)d_in[19];
    const float* bf2 = (const float*)d_in[20];
    const float* l3g = (const float*)d_in[21];
    const float* l3b = (const float*)d_in[22];
    float* out = (float*)d_out;

    float *yr, *xr, *xt, *q, *k, *vt, *sc, *cat, *tmp, *a1, *at2, *a2, *ffh;
    float *wqt, *wkt, *wvt, *w1t, *w2e, *wf1t, *wf2t;
    cudaGetSymbolAddress((void**)&yr,  g_yr);
    cudaGetSymbolAddress((void**)&xr,  g_xr);
    cudaGetSymbolAddress((void**)&xt,  g_xt);
    cudaGetSymbolAddress((void**)&q,   g_q);
    cudaGetSymbolAddress((void**)&k,   g_k);
    cudaGetSymbolAddress((void**)&vt,  g_vt);
    cudaGetSymbolAddress((void**)&sc,  g_sc);
    cudaGetSymbolAddress((void**)&cat, g_cat);
    cudaGetSymbolAddress((void**)&tmp, g_tmp);
    cudaGetSymbolAddress((void**)&a1,  g_a1);
    cudaGetSymbolAddress((void**)&at2, g_at2);
    cudaGetSymbolAddress((void**)&a2,  g_a2);
    cudaGetSymbolAddress((void**)&ffh, g_ffh);
    cudaGetSymbolAddress((void**)&wqt, g_wqt);
    cudaGetSymbolAddress((void**)&wkt, g_wkt);
    cudaGetSymbolAddress((void**)&wvt, g_wvt);
    cudaGetSymbolAddress((void**)&w1t, g_w1t);
    cudaGetSymbolAddress((void**)&w2e, g_w2e);
    cudaGetSymbolAddress((void**)&wf1t, g_wf1t);
    cudaGetSymbolAddress((void**)&wf2t, g_wf2t);

    const int SM128 = 2 * 128 * 128 + 2 * 128 * 128;   // 65536
    const int FSM   = 165888;
    cudaFuncSetAttribute(tc_gemm<128,0,0,0,0>, cudaFuncAttributeMaxDynamicSharedMemorySize, SM128);
    cudaFuncSetAttribute(tc_gemm<128,1,0,0,0>, cudaFuncAttributeMaxDynamicSharedMemorySize, SM128);
    cudaFuncSetAttribute(tc_gemm<128,0,1,0,0>, cudaFuncAttributeMaxDynamicSharedMemorySize, SM128);
    cudaFuncSetAttribute(flash_k, cudaFuncAttributeMaxDynamicSharedMemorySize, FSM);

    const long long SD  = (long long)S_ * D_;
    const long long SS  = (long long)S_ * S_;
    const long long DS  = (long long)D_ * S_;

    // ---------------- prep ----------------
    k_round<<<(BS_ * D_) / 1024, 256>>>(y, yr);
    k_round<<<(BS_ * D_) / 1024, 256>>>(x, xr);
    k_tr<<<dim3(D_/32, S_/32, B_),  256>>>(x,  xt,  S_,  D_,  SD, DS);
    k_tr<<<dim3(DK_/32, D_/32, H_), 256>>>(Wq, wqt, D_,  DK_, (long long)D_*DK_, (long long)DK_*D_);
    k_tr<<<dim3(DK_/32, D_/32, H_), 256>>>(Wk, wkt, D_,  DK_, (long long)D_*DK_, (long long)DK_*D_);
    k_tr<<<dim3(DK_/32, D_/32, H_), 256>>>(Wv, wvt, D_,  DK_, (long long)D_*DK_, (long long)DK_*D_);
    k_tr<<<dim3(D_/32, D_/32, 1),   256>>>(W1, w1t, D_,  D_,  0, 0);
    k_tr<<<dim3(DF_/32, D_/32, 1),  256>>>(Wf1, wf1t, D_, DF_, 0, 0);
    k_tr<<<dim3(D_/32, DF_/32, 1),  256>>>(Wf2, wf2t, DF_, D_, 0, 0);
    k_w2eff<<<dim3(D_/32, D_/32, 1), 256>>>(W2, w2e);

    // ---------------- QKV ----------------
    {
        dim3 g(D_ / 128, S_ / 128, B_);
        tc_gemm<128,0,0,0,0><<<g, 256, SM128>>>(D_,
            yr, D_, SD, 0,  wqt, D_, 0, 0,  q,  D_, SD, 0,  bq, 1, 1.0f);
        tc_gemm<128,0,0,0,0><<<g, 256, SM128>>>(D_,
            yr, D_, SD, 0,  wkt, D_, 0, 0,  k,  D_, SD, 0,  bk, 1, 1.0f);
        tc_gemm<128,1,0,0,0><<<g, 256, SM128>>>(D_,
            yr, D_, SD, 0,  wvt, D_, 0, 0,  vt, S_, DS, 0,  bv, 1, 1.0f);
    }

    // ---------------- fused self-attention ----------------
    flash_k<<<dim3(S_ / 128, H_, B_), 256, FSM>>>(q, k, vt, cat);

    // ---------------- a1 = LN(y + cat @ W1 + b1) ----------------
    tc_gemm<128,0,0,0,0><<<dim3(D_/128, BS_/128, 1), 256, SM128>>>(D_,
        cat, D_, 0, 0,  w1t, D_, 0, 0,  tmp, D_, 0, 0,  b1, 1, 1.0f);
    ln_k<1><<<BS_, 256>>>(y, tmp, l1g, l1b, a1);

    // ---------------- cross scores + softmax ----------------
    tc_gemm<128,0,0,0,0><<<dim3(S_/128, S_/128, B_), 256, SM128>>>(D_,
        a1, D_, SD, 0,  xr, D_, SD, 0,  sc, S_, SS, 0,  nullptr, 1, SCALE_);
    softmax_k<<<B_ * S_, 256>>>(sc);

    // ---------------- attn2 = P @ x ----------------
    tc_gemm<128,0,0,0,0><<<dim3(D_/128, S_/128, B_), 256, SM128>>>(S_,
        sc, S_, SS, 0,  xt, S_, DS, 0,  at2, D_, SD, 0,  nullptr, 1, 1.0f);

    // ---------------- a2 = LN(y + attn2 @ W2_eff + b2) ----------------
    tc_gemm<128,0,0,0,0><<<dim3(D_/128, BS_/128, 1), 256, SM128>>>(D_,
        at2, D_, 0, 0,  w2e, D_, 0, 0,  tmp, D_, 0, 0,  b2, 1, 1.0f);
    ln_k<1><<<BS_, 256>>>(y, tmp, l2g, l2b, a2);

    // ---------------- FFN ----------------
    tc_gemm<128,0,1,0,0><<<dim3(DF_/128, BS_/128, 1), 256, SM128>>>(D_,
        a2, D_, 0, 0,  wf1t, D_, 0, 0,  ffh, DF_, 0, 0,  bf1, 1, 1.0f);
    tc_gemm<128,0,0,0,0><<<dim3(D_/128, BS_/128, 1), 256, SM128>>>(DF_,
        ffh, DF_, 0, 0,  wf2t, DF_, 0, 0,  tmp, D_, 0, 0,  bf2, 1, 1.0f);
    ln_k<0><<<BS_, 256>>>(y, tmp, l3g, l3b, out);
}

// round 11
// speedup vs baseline: 4.9900x; 1.0769x over previous
#include <cuda_runtime.h>
#include <cstdint>
#include <math.h>

// ---------------------------------------------------------------------------
// DecoderLayer: B=2, S=2048, D=1024, H=16, DF=4096, DK=64
// Round 11: 64x64-warp 3-stage tf32 GEMM (1 sync/tile, 2 CTA/SM),
// flash self-attn with double-buffered KV prefetch + reversed scheduling,
// merged Q+K projection (N=2048).
// ---------------------------------------------------------------------------

#define B_  2
#define S_  2048
#define D_  1024
#define H_  16
#define DF_ 4096
#define DK_ 64
#define BS_ (B_*S_)
#define QK2 2048
#define SCALE_ 0.125f
#define EPS_   1e-5f

// -------------------------- scratch (static device) -------------------------
__device__ float g_yr [(size_t)BS_*D_];
__device__ float g_xr [(size_t)BS_*D_];
__device__ float g_xt [(size_t)B_*D_*S_];
__device__ float g_qk [(size_t)B_*S_*QK2];   // [b][s][q(1024) | k(1024)]
__device__ float g_vt [(size_t)B_*D_*S_];    // v^T [b][h*64+dk][s]
__device__ float g_sc [(size_t)B_*S_*S_];    // cross-attn scores
__device__ float g_cat[(size_t)BS_*D_];
__device__ float g_tmp[(size_t)BS_*D_];
__device__ float g_a1 [(size_t)BS_*D_];
__device__ float g_at2[(size_t)BS_*D_];
__device__ float g_a2 [(size_t)BS_*D_];
__device__ float g_ffh[(size_t)BS_*DF_];
__device__ float g_wqkt[(size_t)2*D_*D_];    // [Wq^T | Wk^T] rows 0..2047
__device__ float g_bqk [QK2];
__device__ float g_wvt[(size_t)D_*D_];
__device__ float g_w1t[(size_t)D_*D_];
__device__ float g_w2e[(size_t)D_*D_];
__device__ float g_wf1t[(size_t)DF_*D_];
__device__ float g_wf2t[(size_t)D_*DF_];

// ------------------------------ PTX helpers ---------------------------------
__device__ __forceinline__ uint32_t smem_u32(const void* p) {
    uint32_t a;
    asm("{ .reg .u64 t; cvta.to.shared.u64 t, %1; cvt.u32.u64 %0, t; }"
        : "=r"(a) : "l"(p));
    return a;
}
__device__ __forceinline__ float tf32f(float f) {
    uint32_t r;
    asm("cvt.rna.tf32.f32 %0, %1;" : "=r"(r) : "f"(f));
    return __uint_as_float(r);
}
#define CP16(dst, src) \
    asm volatile("cp.async.cg.shared.global [%0], [%1], 16;" \
                 :: "r"(dst), "l"(src))
#define CP_COMMIT() asm volatile("cp.async.commit_group;" ::: "memory")
#define CP_WAIT0()  asm volatile("cp.async.wait_group 0;" ::: "memory")
#define CP_WAIT1()  asm volatile("cp.async.wait_group 1;" ::: "memory")
#define LDSM4(r0,r1,r2,r3,addr) \
    asm volatile("ldmatrix.sync.aligned.m8n8.x4.shared.b16 {%0,%1,%2,%3}, [%4];" \
                 : "=r"(r0),"=r"(r1),"=r"(r2),"=r"(r3) : "r"(addr))
#define MMA8(d, a0,a1,a2,a3, b0,b1) \
    asm volatile("mma.sync.aligned.m16n8k8.row.col.f32.tf32.tf32.f32 " \
                 "{%0,%1,%2,%3},{%4,%5,%6,%7},{%8,%9},{%0,%1,%2,%3};" \
                 : "+f"(d[0]),"+f"(d[1]),"+f"(d[2]),"+f"(d[3]) \
                 : "r"(a0),"r"(a1),"r"(a2),"r"(a3),"r"(b0),"r"(b1))

// ------------------------------- tensor GEMM --------------------------------
// C[z] = alpha * A[z] @ B[z]^T (+bias)(,relu).  BM=BN=128, BK=32.
// 4 warps, warp tile 64x64. 3-stage cp.async pipeline, one sync per tile.
// A: [M][K] row-major; B: [N][K] row-major (k-major, pre-transposed).
// TRC: write C transposed (C[n][m]).
template<int TRC,int RELU>
__global__ __launch_bounds__(128,2)
void tc_gemm(int K,
             const float* __restrict__ A,  int lda, long long sA,
             const float* __restrict__ Bg, int ldb, long long sB,
             float* __restrict__ C,        int ldc, long long sC,
             const float* __restrict__ bias, float alpha)
{
    constexpr int STAGE = 32768;      // 16KB A + 16KB B per stage
    constexpr int OFF_B = 16384;

    const int m0 = blockIdx.y * 128;
    const int n0 = blockIdx.x * 128;
    extern __shared__ __align__(1024) char smem[];
    const uint32_t sbase = smem_u32(smem);
    const int tid = threadIdx.x, wid = tid >> 5, lane = tid & 31;

    const long long z = blockIdx.z;
    A  += z * sA;
    Bg += z * sB;
    C  += z * sC;

    const int T = K >> 5;

    auto stage = [&](int s, int k0) {
        const float* Ab = A + (size_t)m0 * lda + k0;
        const uint32_t sa = sbase + s * STAGE;
        #pragma unroll
        for (int it = 0; it < 8; it++) {
            int idx = tid + (it << 7);
            int row = idx >> 3, c4 = (idx & 7) << 2;
            uint32_t off = ((uint32_t)row << 7) + ((uint32_t)c4 << 2);
            off ^= (off >> 3) & 0x70;
            CP16(sa + off, Ab + (size_t)row * lda + c4);
        }
        const float* Bb = Bg + (size_t)n0 * ldb + k0;
        const uint32_t sb = sbase + s * STAGE + OFF_B;
        #pragma unroll
        for (int it = 0; it < 8; it++) {
            int idx = tid + (it << 7);
            int row = idx >> 3, c4 = (idx & 7) << 2;
            uint32_t off = ((uint32_t)row << 7) + ((uint32_t)c4 << 2);
            off ^= (off >> 3) & 0x70;
            CP16(sb + off, Bb + (size_t)row * ldb + c4);
        }
    };

    // fragment addressing (64x64 warp tile; 2 M-warps x 2 N-warps)
    const int mw = wid & 1, nw = wid >> 1;
    const int mbase = mw * 64, nbase = nw * 64;
    const int swz = lane & 7;
    const int caA = (lane >> 4) & 1;
    const int caB = (lane >> 3) & 1;
    uint32_t aoffb[4], boffb[4];
    {
        int ar0 = mbase + (lane & 7) + (((lane >> 3) & 1) << 3);
        #pragma unroll
        for (int mt = 0; mt < 4; mt++) aoffb[mt] = (uint32_t)(ar0 + mt * 16) << 7;
        int br0 = nbase + (lane & 7) + (((lane >> 4) & 1) << 3);
        #pragma unroll
        for (int p = 0; p < 4; p++) boffb[p] = (uint32_t)(br0 + p * 16) << 7;
    }

    float acc[4][8][4];
    #pragma unroll
    for (int mt = 0; mt < 4; mt++)
        #pragma unroll
        for (int nt = 0; nt < 8; nt++)
            #pragma unroll
            for (int j = 0; j < 4; j++) acc[mt][nt][j] = 0.0f;

    // prologue: stage tiles 0,1
    stage(0, 0);
    CP_COMMIT();
    if (T > 1) { stage(1, 32); CP_COMMIT(); }

    int buf = 0;
    for (int t = 0; t < T; t++) {
        if (t + 1 < T) CP_WAIT1(); else CP_WAIT0();
        __syncthreads();

        const uint32_t aB = sbase + buf * STAGE;
        const uint32_t bB = aB + OFF_B;
        #pragma unroll
        for (int kc = 0; kc < 4; kc++) {
            const uint32_t swa = (uint32_t)(((2 * kc + caA) ^ swz) << 4);
            const uint32_t swb = (uint32_t)(((2 * kc + caB) ^ swz) << 4);
            uint32_t af[4][4], bf[4][4];
            #pragma unroll
            for (int mt = 0; mt < 4; mt++)
                LDSM4(af[mt][0], af[mt][1], af[mt][2], af[mt][3],
                      aB + aoffb[mt] + swa);
            #pragma unroll
            for (int p = 0; p < 4; p++)
                LDSM4(bf[p][0], bf[p][1], bf[p][2], bf[p][3],
                      bB + boffb[p] + swb);
            #pragma unroll
            for (int mt = 0; mt < 4; mt++)
                #pragma unroll
                for (int p = 0; p < 4; p++) {
                    MMA8(acc[mt][2 * p],     af[mt][0], af[mt][1], af[mt][2], af[mt][3],
                         bf[p][0], bf[p][1]);
                    MMA8(acc[mt][2 * p + 1], af[mt][0], af[mt][1], af[mt][2], af[mt][3],
                         bf[p][2], bf[p][3]);
                }
        }
        // stage tile t+2 into buffer (t+2)%3 — all warps finished reading it
        // at iteration t-1 (guarded by this iteration's barrier).
        const int s = t + 2;
        if (s < T) {
            int sb = buf + 2; if (sb >= 3) sb -= 3;
            stage(sb, s << 5);
            CP_COMMIT();
        }
        if (++buf == 3) buf = 0;
    }

    // epilogue
    const int g = lane >> 2, tg = lane & 3;
    #pragma unroll
    for (int mt = 0; mt < 4; mt++) {
        const int r0 = m0 + mbase + mt * 16 + g;
        #pragma unroll
        for (int nt = 0; nt < 8; nt++) {
            const int col = n0 + nbase + nt * 8 + tg * 2;
            float v0 = acc[mt][nt][0] * alpha, v1 = acc[mt][nt][1] * alpha;
            float v2 = acc[mt][nt][2] * alpha, v3 = acc[mt][nt][3] * alpha;
            if (bias) {
                float b0 = bias[col], b1 = bias[col + 1];
                v0 += b0; v1 += b1; v2 += b0; v3 += b1;
            }
            if (RELU) {
                v0 = fmaxf(v0, 0.f); v1 = fmaxf(v1, 0.f);
                v2 = fmaxf(v2, 0.f); v3 = fmaxf(v3, 0.f);
            }
            v0 = tf32f(v0); v1 = tf32f(v1); v2 = tf32f(v2); v3 = tf32f(v3);
            if (!TRC) {
                *(float2*)(C + (size_t)r0 * ldc + col)       = make_float2(v0, v1);
                *(float2*)(C + (size_t)(r0 + 8) * ldc + col) = make_float2(v2, v3);
            } else {
                C[(size_t)col       * ldc + r0]     = v0;
                C[(size_t)(col + 1) * ldc + r0]     = v1;
                C[(size_t)col       * ldc + r0 + 8] = v2;
                C[(size_t)(col + 1) * ldc + r0 + 8] = v3;
            }
        }
    }
}

// --------------------------- flash self-attention ----------------------------
// Per CTA: 128 q-rows of one (b,h). K/V double-buffered; prefetch of tile
// kb+1 is issued before the compute of tile kb. qb reversed so the longest
// (most key tiles) CTAs schedule first.
__global__ __launch_bounds__(256)
void flash_k(const float* __restrict__ qkg, const float* __restrict__ vtg,
             float* __restrict__ catg)
{
    constexpr int OFF_Q = 0;                 // 2 x [128][32] = 32KB
    constexpr int OFF_K = 32768;             // 2 bufs x 32KB
    constexpr int OFF_V = 98304;             // 2 bufs x 32KB
    constexpr int OFF_P = 163840;            // 4 x [128][32] = 64KB
    constexpr int OFF_PM = 229376;           // [2][128] f32
    constexpr int OFF_PL = 230400;           // [2][128] f32

    const int qb = (int)gridDim.x - 1 - (int)blockIdx.x;
    const int h = blockIdx.y, b = blockIdx.z;
    extern __shared__ __align__(1024) char smem[];
    const uint32_t sbase = smem_u32(smem);
    const int tid = threadIdx.x, wid = tid >> 5, lane = tid & 31;
    const int mw = wid & 3, nw = wid >> 2;
    const int mbase = mw * 32;
    const int nbS = nw * 64;
    const int nbV = nw * 32;
    const int g = lane >> 2, tg = lane & 3;
    const int swz = lane & 7;
    const int caA = (lane >> 4) & 1, caB = (lane >> 3) & 1;

    const size_t SQ = (size_t)S_ * QK2;
    const float* Qs = qkg + (size_t)b * SQ + (size_t)(qb * 128) * QK2 + h * 64;
    const float* Ks = qkg + (size_t)b * SQ + 1024 + h * 64;
    const float* Vs = vtg + (size_t)b * ((size_t)D_ * S_) + (size_t)(h * 64) * S_;

    uint32_t aoffb[2], boffS[4], boffV[2];
    {
        int ar0 = mbase + (lane & 7) + (((lane >> 3) & 1) << 3);
        aoffb[0] = (uint32_t)ar0 << 7;
        aoffb[1] = (uint32_t)(ar0 + 16) << 7;
        int br0 = nbS + (lane & 7) + (((lane >> 4) & 1) << 3);
        #pragma unroll
        for (int p = 0; p < 4; p++) boffS[p] = (uint32_t)(br0 + p * 16) << 7;
        int bv0 = nbV + (lane & 7) + (((lane >> 4) & 1) << 3);
        boffV[0] = (uint32_t)bv0 << 7;
        boffV[1] = (uint32_t)(bv0 + 16) << 7;
    }

    auto stageKV = [&](int bufd, int kb) {
        const uint32_t kB = sbase + OFF_K + bufd * 32768;
        #pragma unroll
        for (int c = 0; c < 2; c++)
            #pragma unroll
            for (int it = 0; it < 4; it++) {
                int idx = tid + (it << 8);
                int row = idx >> 3, c4 = (idx & 7) << 2;
                uint32_t off = ((uint32_t)row << 7) + ((uint32_t)c4 << 2);
                off ^= (off >> 3) & 0x70;
                CP16(kB + c * 16384 + off,
                     Ks + (size_t)(kb * 128 + row) * QK2 + c * 32 + c4);
            }
        const uint32_t vB = sbase + OFF_V + bufd * 32768;
        #pragma unroll
        for (int c = 0; c < 4; c++)
            #pragma unroll
            for (int it = 0; it < 2; it++) {
                int idx = tid + (it << 8);
                int row = idx >> 3, c4 = (idx & 7) << 2;
                uint32_t off = ((uint32_t)row << 7) + ((uint32_t)c4 << 2);
                off ^= (off >> 3) & 0x70;
                CP16(vB + c * 8192 + off,
                     Vs + (size_t)row * S_ + kb * 128 + c * 32 + c4);
            }
    };

    // ---- stage Q (resident) + first K/V tile ----
    #pragma unroll
    for (int c = 0; c < 2; c++)
        #pragma unroll
        for (int it = 0; it < 4; it++) {
            int idx = tid + (it << 8);
            int row = idx >> 3, c4 = (idx & 7) << 2;
            uint32_t off = ((uint32_t)row << 7) + ((uint32_t)c4 << 2);
            off ^= (off >> 3) & 0x70;
            CP16(sbase + OFF_Q + c * 16384 + off, Qs + (size_t)row * QK2 + c * 32 + c4);
        }
    stageKV(0, 0);
    CP_COMMIT();

    float oacc[2][4][4];
    #pragma unroll
    for (int mt = 0; mt < 2; mt++)
        #pragma unroll
        for (int nt = 0; nt < 4; nt++)
            #pragma unroll
            for (int j = 0; j < 4; j++) oacc[mt][nt][j] = 0.0f;
    float m_run[2][2] = {{-1e30f, -1e30f}, {-1e30f, -1e30f}};
    float l_run[2][2] = {{0.f, 0.f}, {0.f, 0.f}};
    float* pm = (float*)(smem + OFF_PM);
    float* pl = (float*)(smem + OFF_PL);

    for (int kb = 0; kb <= qb; kb++) {
        const int bufc = kb & 1;
        CP_WAIT0();
        __syncthreads();
        if (kb < qb) { stageKV(bufc ^ 1, kb + 1); CP_COMMIT(); }

        // ---- S = Q @ K^T (warp 32x64) ----
        float sacc[2][8][4];
        #pragma unroll
        for (int mt = 0; mt < 2; mt++)
            #pragma unroll
            for (int nt = 0; nt < 8; nt++)
                #pragma unroll
                for (int j = 0; j < 4; j++) sacc[mt][nt][j] = 0.0f;
        #pragma unroll
        for (int ch = 0; ch < 2; ch++) {
            const uint32_t aB = sbase + OFF_Q + ch * 16384;
            const uint32_t bB = sbase + OFF_K + bufc * 32768 + ch * 16384;
            #pragma unroll
            for (int kc = 0; kc < 4; kc++) {
                const uint32_t swa = (uint32_t)(((2 * kc + caA) ^ swz) << 4);
                const uint32_t swb = (uint32_t)(((2 * kc + caB) ^ swz) << 4);
                uint32_t af[2][4], bf[4][4];
                #pragma unroll
                for (int mt = 0; mt < 2; mt++)
                    LDSM4(af[mt][0], af[mt][1], af[mt][2], af[mt][3],
                          aB + aoffb[mt] + swa);
                #pragma unroll
                for (int p = 0; p < 4; p++)
                    LDSM4(bf[p][0], bf[p][1], bf[p][2], bf[p][3],
                          bB + boffS[p] + swb);
                #pragma unroll
                for (int mt = 0; mt < 2; mt++)
                    #pragma unroll
                    for (int p = 0; p < 4; p++) {
                        MMA8(sacc[mt][2 * p],     af[mt][0], af[mt][1], af[mt][2], af[mt][3],
                             bf[p][0], bf[p][1]);
                        MMA8(sacc[mt][2 * p + 1], af[mt][0], af[mt][1], af[mt][2], af[mt][3],
                             bf[p][2], bf[p][3]);
                    }
            }
        }

        // ---- scale + causal mask + row max ----
        const bool diag = (kb == qb);
        float tmx[2][2] = {{-1e30f, -1e30f}, {-1e30f, -1e30f}};
        #pragma unroll
        for (int mt = 0; mt < 2; mt++)
            #pragma unroll
            for (int nt = 0; nt < 8; nt++)
                #pragma unroll
                for (int j = 0; j < 4; j++) {
                    float v = sacc[mt][nt][j] * SCALE_;
                    if (diag) {
                        int cl = nbS + nt * 8 + tg * 2 + (j & 1);
                        int rl = mbase + mt * 16 + g + ((j & 2) << 2);
                        if (cl > rl) v = -1e30f;
                    }
                    sacc[mt][nt][j] = v;
                    tmx[mt][j >> 1] = fmaxf(tmx[mt][j >> 1], v);
                }
        #pragma unroll
        for (int mt = 0; mt < 2; mt++)
            #pragma unroll
            for (int hh = 0; hh < 2; hh++) {
                float t = tmx[mt][hh];
                t = fmaxf(t, __shfl_xor_sync(0xffffffffu, t, 1));
                t = fmaxf(t, __shfl_xor_sync(0xffffffffu, t, 2));
                if (tg == 0)
                    pm[nw * 128 + mbase + mt * 16 + hh * 8 + g] = t;
            }
        __syncthreads();

        float cf[2][2], mnew[2][2];
        #pragma unroll
        for (int mt = 0; mt < 2; mt++)
            #pragma unroll
            for (int hh = 0; hh < 2; hh++) {
                int r = mbase + mt * 16 + hh * 8 + g;
                float tm = fmaxf(pm[r], pm[128 + r]);
                float mn = fmaxf(m_run[mt][hh], tm);
                cf[mt][hh] = __expf(m_run[mt][hh] - mn);
                m_run[mt][hh] = mn;
                mnew[mt][hh] = mn;
            }

        // ---- exp + P store (tf32) + partial sums ----
        float ts[2][2] = {{0.f, 0.f}, {0.f, 0.f}};
        #pragma unroll
        for (int mt = 0; mt < 2; mt++) {
            const int r0 = mbase + mt * 16 + g;
            #pragma unroll
            for (int nt = 0; nt < 8; nt++) {
                const int col = nbS + nt * 8 + tg * 2;
                float p0 = __expf(sacc[mt][nt][0] - mnew[mt][0]);
                float p1 = __expf(sacc[mt][nt][1] - mnew[mt][0]);
                float p2 = __expf(sacc[mt][nt][2] - mnew[mt][1]);
                float p3 = __expf(sacc[mt][nt][3] - mnew[mt][1]);
                ts[mt][0] += p0 + p1;
                ts[mt][1] += p2 + p3;
                uint32_t off0 = (uint32_t)(col >> 5) * 16384 +
                                ((uint32_t)r0 << 7) + ((uint32_t)(col & 31) << 2);
                off0 ^= (off0 >> 3) & 0x70;
                *(float2*)(smem + OFF_P + off0) = make_float2(tf32f(p0), tf32f(p1));
                uint32_t off1 = (uint32_t)(col >> 5) * 16384 +
                                ((uint32_t)(r0 + 8) << 7) + ((uint32_t)(col & 31) << 2);
                off1 ^= (off1 >> 3) & 0x70;
                *(float2*)(smem + OFF_P + off1) = make_float2(tf32f(p2), tf32f(p3));
            }
        }
        #pragma unroll
        for (int mt = 0; mt < 2; mt++)
            #pragma unroll
            for (int hh = 0; hh < 2; hh++) {
                float t = ts[mt][hh];
                t += __shfl_xor_sync(0xffffffffu, t, 1);
                t += __shfl_xor_sync(0xffffffffu, t, 2);
                if (tg == 0)
                    pl[nw * 128 + mbase + mt * 16 + hh * 8 + g] = t;
            }
        __syncthreads();

        #pragma unroll
        for (int mt = 0; mt < 2; mt++)
            #pragma unroll
            for (int hh = 0; hh < 2; hh++) {
                int r = mbase + mt * 16 + hh * 8 + g;
                l_run[mt][hh] = l_run[mt][hh] * cf[mt][hh] + pl[r] + pl[128 + r];
            }
        #pragma unroll
        for (int mt = 0; mt < 2; mt++)
            #pragma unroll
            for (int nt = 0; nt < 4; nt++)
                #pragma unroll
                for (int j = 0; j < 4; j++)
                    oacc[mt][nt][j] *= cf[mt][j >> 1];

        // ---- O += P @ V (warp 32x32) ----
        #pragma unroll
        for (int ch = 0; ch < 4; ch++) {
            const uint32_t aB = sbase + OFF_P + ch * 16384;
            const uint32_t bB = sbase + OFF_V + bufc * 32768 + ch * 8192;
            #pragma unroll
            for (int kc = 0; kc < 4; kc++) {
                const uint32_t swa = (uint32_t)(((2 * kc + caA) ^ swz) << 4);
                const uint32_t swb = (uint32_t)(((2 * kc + caB) ^ swz) << 4);
                uint32_t af[2][4], bf[2][4];
                #pragma unroll
                for (int mt = 0; mt < 2; mt++)
                    LDSM4(af[mt][0], af[mt][1], af[mt][2], af[mt][3],
                          aB + aoffb[mt] + swa);
                #pragma unroll
                for (int p = 0; p < 2; p++)
                    LDSM4(bf[p][0], bf[p][1], bf[p][2], bf[p][3],
                          bB + boffV[p] + swb);
                #pragma unroll
                for (int mt = 0; mt < 2; mt++)
                    #pragma unroll
                    for (int p = 0; p < 2; p++) {
                        MMA8(oacc[mt][2 * p],     af[mt][0], af[mt][1], af[mt][2], af[mt][3],
                             bf[p][0], bf[p][1]);
                        MMA8(oacc[mt][2 * p + 1], af[mt][0], af[mt][1], af[mt][2], af[mt][3],
                             bf[p][2], bf[p][3]);
                    }
            }
        }
        __syncthreads();   // protect P / pm / pl before next tile
    }

    // ---- epilogue: O / l -> cat (tf32-rounded) ----
    float* dst = catg + (size_t)b * ((size_t)S_ * D_) + (size_t)(qb * 128) * D_ + h * 64;
    #pragma unroll
    for (int mt = 0; mt < 2; mt++) {
        const int r0 = mbase + mt * 16 + g;
        const float i0 = 1.0f / l_run[mt][0];
        const float i1 = 1.0f / l_run[mt][1];
        #pragma unroll
        for (int nt = 0; nt < 4; nt++) {
            const int col = nbV + nt * 8 + tg * 2;
            *(float2*)(dst + (size_t)r0 * D_ + col) =
                make_float2(tf32f(oacc[mt][nt][0] * i0), tf32f(oacc[mt][nt][1] * i0));
            *(float2*)(dst + (size_t)(r0 + 8) * D_ + col) =
                make_float2(tf32f(oacc[mt][nt][2] * i1), tf32f(oacc[mt][nt][3] * i1));
        }
    }
}

// ------------------------------ softmax (cross) ------------------------------
__global__ __launch_bounds__(256)
void softmax_k(float* __restrict__ sc)
{
    __shared__ float buf[S_];
    __shared__ float red[256];
    const int row = blockIdx.x;
    const int tid = threadIdx.x;
    float* p = sc + (size_t)row * S_;

    float mx = -3.0e38f;
    for (int t = tid; t < S_; t += 256) {
        float vv = p[t];
        buf[t] = vv;
        mx = fmaxf(mx, vv);
    }
    red[tid] = mx;
    __syncthreads();
    for (int o = 128; o > 0; o >>= 1) {
        if (tid < o) red[tid] = fmaxf(red[tid], red[tid + o]);
        __syncthreads();
    }
    mx = red[0];
    __syncthreads();

    float sum = 0.0f;
    for (int t = tid; t < S_; t += 256) {
        float e = __expf(buf[t] - mx);
        buf[t] = e;
        sum += e;
    }
    red[tid] = sum;
    __syncthreads();
    for (int o = 128; o > 0; o >>= 1) {
        if (tid < o) red[tid] += red[tid + o];
        __syncthreads();
    }
    const float inv = 1.0f / red[0];

    for (int t = tid; t < S_; t += 256)
        p[t] = tf32f(buf[t] * inv);
}

// ------------------------- residual + LayerNorm ------------------------------
template<int RND>
__global__ __launch_bounds__(256)
void ln_k(const float* __restrict__ y, const float* __restrict__ t,
          const float* __restrict__ g, const float* __restrict__ bb,
          float* __restrict__ out)
{
    const int row = blockIdx.x;
    const int tid = threadIdx.x;
    const float* yr = y + (size_t)row * D_;
    const float* tr = t + (size_t)row * D_;

    float vloc[4];
    float s = 0.0f, s2 = 0.0f;
    #pragma unroll
    for (int i = 0; i < 4; i++) {
        int c = tid + i * 256;
        float vv = yr[c] + tr[c];
        vloc[i] = vv;
        s  += vv;
        s2 += vv * vv;
    }
    __shared__ float rs[256], rq[256];
    rs[tid] = s; rq[tid] = s2;
    __syncthreads();
    for (int o = 128; o > 0; o >>= 1) {
        if (tid < o) { rs[tid] += rs[tid + o]; rq[tid] += rq[tid + o]; }
        __syncthreads();
    }
    const float mean = rs[0] * (1.0f / D_);
    const float var  = rq[0] * (1.0f / D_) - mean * mean;
    const float inv  = rsqrtf(var + EPS_);

    float* orow = out + (size_t)row * D_;
    #pragma unroll
    for (int i = 0; i < 4; i++) {
        int c = tid + i * 256;
        float o = (vloc[i] - mean) * inv * g[c] + bb[c];
        orow[c] = RND ? tf32f(o) : o;
    }
}

// ------------------------------ prep kernels ---------------------------------
__global__ __launch_bounds__(256)
void k_round(const float* __restrict__ in, float* __restrict__ out)
{
    int i = blockIdx.x * 256 + threadIdx.x;
    float4 v = ((const float4*)in)[i];
    v.x = tf32f(v.x); v.y = tf32f(v.y); v.z = tf32f(v.z); v.w = tf32f(v.w);
    ((float4*)out)[i] = v;
}

__global__ __launch_bounds__(256)
void k_tr(const float* __restrict__ in, float* __restrict__ out,
          int R, int C, long long si, long long so)
{
    __shared__ float t[32][33];
    in  += (size_t)blockIdx.z * si;
    out += (size_t)blockIdx.z * so;
    const int r0 = blockIdx.y * 32, c0 = blockIdx.x * 32;
    const int tx = threadIdx.x & 31, ty = threadIdx.x >> 5;
    #pragma unroll
    for (int j = 0; j < 4; j++)
        t[ty + j * 8][tx] = in[(size_t)(r0 + ty + j * 8) * C + c0 + tx];
    __syncthreads();
    #pragma unroll
    for (int j = 0; j < 4; j++)
        out[(size_t)(c0 + ty + j * 8) * R + r0 + tx] = tf32f(t[tx][ty + j * 8]);
}

__global__ __launch_bounds__(256)
void k_w2eff(const float* __restrict__ W2, float* __restrict__ o)
{
    __shared__ float t[32][33];
    const int d0 = blockIdx.y * 32, c0 = blockIdx.x * 32;
    const int tx = threadIdx.x & 31, ty = threadIdx.x >> 5;
    float r[4] = {0.f, 0.f, 0.f, 0.f};
    for (int h = 0; h < H_; h++) {
        #pragma unroll
        for (int j = 0; j < 4; j++)
            r[j] += W2[(size_t)(h * D_ + d0 + ty + j * 8) * D_ + c0 + tx];
    }
    #pragma unroll
    for (int j = 0; j < 4; j++) t[ty + j * 8][tx] = r[j];
    __syncthreads();
    #pragma unroll
    for (int j = 0; j < 4; j++)
        o[(size_t)(c0 + ty + j * 8) * D_ + d0 + tx] = tf32f(t[tx][ty + j * 8]);
}

__global__ __launch_bounds__(256)
void k_bcat(const float* __restrict__ bq, const float* __restrict__ bk,
            float* __restrict__ o)
{
    int i = blockIdx.x * 256 + threadIdx.x;
    o[i] = (i < 1024) ? bq[i] : bk[i - 1024];
}

// ------------------------------ launcher -------------------------------------
extern "C" void kernel_launch(void* const* d_in, const int* in_sizes, int n_in,
                              void* d_out, int out_size)
{
    const float* x   = (const float*)d_in[0];
    const float* y   = (const float*)d_in[1];
    // d_in[2] = y_mask (causal tril) — analytic
    const float* Wq  = (const float*)d_in[3];
    const float* bq  = (const float*)d_in[4];
    const float* Wk  = (const float*)d_in[5];
    const float* bk  = (const float*)d_in[6];
    const float* Wv  = (const float*)d_in[7];
    const float* bv  = (const float*)d_in[8];
    const float* W1  = (const float*)d_in[9];
    const float* b1  = (const float*)d_in[10];
    const float* l1g = (const float*)d_in[11];
    const float* l1b = (const float*)d_in[12];
    const float* W2  = (const float*)d_in[13];
    const float* b2  = (const float*)d_in[14];
    const float* l2g = (const float*)d_in[15];
    const float* l2b = (const float*)d_in[16];
    const float* Wf1 = (const float*)d_in[17];
    const float* bf1 = (const float*)d_in[18];
    const float* Wf2 = (const float*)d_in[19];
    const float* bf2 = (const float*)d_in[20];
    const float* l3g = (const float*)d_in[21];
    const float* l3b = (const float*)d_in[22];
    float* out = (float*)d_out;

    float *yr, *xr, *xt, *qk, *vt, *sc, *cat, *tmp, *a1, *at2, *a2, *ffh;
    float *wqkt, *bqk, *wvt, *w1t, *w2e, *wf1t, *wf2t;
    cudaGetSymbolAddress((void**)&yr,   g_yr);
    cudaGetSymbolAddress((void**)&xr,   g_xr);
    cudaGetSymbolAddress((void**)&xt,   g_xt);
    cudaGetSymbolAddress((void**)&qk,   g_qk);
    cudaGetSymbolAddress((void**)&vt,   g_vt);
    cudaGetSymbolAddress((void**)&sc,   g_sc);
    cudaGetSymbolAddress((void**)&cat,  g_cat);
    cudaGetSymbolAddress((void**)&tmp,  g_tmp);
    cudaGetSymbolAddress((void**)&a1,   g_a1);
    cudaGetSymbolAddress((void**)&at2,  g_at2);
    cudaGetSymbolAddress((void**)&a2,   g_a2);
    cudaGetSymbolAddress((void**)&ffh,  g_ffh);
    cudaGetSymbolAddress((void**)&wqkt, g_wqkt);
    cudaGetSymbolAddress((void**)&bqk,  g_bqk);
    cudaGetSymbolAddress((void**)&wvt,  g_wvt);
    cudaGetSymbolAddress((void**)&w1t,  g_w1t);
    cudaGetSymbolAddress((void**)&w2e,  g_w2e);
    cudaGetSymbolAddress((void**)&wf1t, g_wf1t);
    cudaGetSymbolAddress((void**)&wf2t, g_wf2t);

    const int GSM = 3 * 32768;        // 96KB, 3-stage
    const int FSM = 231424;           // flash
    cudaFuncSetAttribute(tc_gemm<0,0>, cudaFuncAttributeMaxDynamicSharedMemorySize, GSM);
    cudaFuncSetAttribute(tc_gemm<1,0>, cudaFuncAttributeMaxDynamicSharedMemorySize, GSM);
    cudaFuncSetAttribute(tc_gemm<0,1>, cudaFuncAttributeMaxDynamicSharedMemorySize, GSM);
    cudaFuncSetAttribute(flash_k, cudaFuncAttributeMaxDynamicSharedMemorySize, FSM);

    const long long SD  = (long long)S_ * D_;
    const long long SS  = (long long)S_ * S_;
    const long long DS  = (long long)D_ * S_;
    const long long SQK = (long long)S_ * QK2;

    // ---------------- prep ----------------
    k_round<<<(BS_ * D_) / 1024, 256>>>(y, yr);
    k_round<<<(BS_ * D_) / 1024, 256>>>(x, xr);
    k_tr<<<dim3(D_/32, S_/32, B_),  256>>>(x,  xt,  S_,  D_,  SD, DS);
    k_tr<<<dim3(DK_/32, D_/32, H_), 256>>>(Wq, wqkt,           D_, DK_, (long long)D_*DK_, (long long)DK_*D_);
    k_tr<<<dim3(DK_/32, D_/32, H_), 256>>>(Wk, wqkt + (size_t)D_*D_, D_, DK_, (long long)D_*DK_, (long long)DK_*D_);
    k_tr<<<dim3(DK_/32, D_/32, H_), 256>>>(Wv, wvt, D_,  DK_, (long long)D_*DK_, (long long)DK_*D_);
    k_tr<<<dim3(D_/32, D_/32, 1),   256>>>(W1, w1t, D_,  D_,  0, 0);
    k_tr<<<dim3(DF_/32, D_/32, 1),  256>>>(Wf1, wf1t, D_, DF_, 0, 0);
    k_tr<<<dim3(D_/32, DF_/32, 1),  256>>>(Wf2, wf2t, DF_, D_, 0, 0);
    k_w2eff<<<dim3(D_/32, D_/32, 1), 256>>>(W2, w2e);
    k_bcat<<<QK2 / 256, 256>>>(bq, bk, bqk);

    // ---------------- Q+K merged projection (N=2048) ----------------
    tc_gemm<0,0><<<dim3(QK2/128, S_/128, B_), 128, GSM>>>(D_,
        yr, D_, SD,  wqkt, D_, 0,  qk, QK2, SQK,  bqk, 1.0f);

    // ---------------- V projection (transposed output) ----------------
    tc_gemm<1,0><<<dim3(D_/128, S_/128, B_), 128, GSM>>>(D_,
        yr, D_, SD,  wvt, D_, 0,  vt, S_, DS,  bv, 1.0f);

    // ---------------- fused self-attention ----------------
    flash_k<<<dim3(S_ / 128, H_, B_), 256, FSM>>>(qk, vt, cat);

    // ---------------- a1 = LN(y + cat @ W1 + b1) ----------------
    tc_gemm<0,0><<<dim3(D_/128, BS_/128, 1), 128, GSM>>>(D_,
        cat, D_, 0,  w1t, D_, 0,  tmp, D_, 0,  b1, 1.0f);
    ln_k<1><<<BS_, 256>>>(y, tmp, l1g, l1b, a1);

    // ---------------- cross scores + softmax ----------------
    tc_gemm<0,0><<<dim3(S_/128, S_/128, B_), 128, GSM>>>(D_,
        a1, D_, SD,  xr, D_, SD,  sc, S_, SS,  nullptr, SCALE_);
    softmax_k<<<B_ * S_, 256>>>(sc);

    // ---------------- attn2 = P @ x ----------------
    tc_gemm<0,0><<<dim3(D_/128, S_/128, B_), 128, GSM>>>(S_,
        sc, S_, SS,  xt, S_, DS,  at2, D_, SD,  nullptr, 1.0f);

    // ---------------- a2 = LN(y + attn2 @ W2_eff + b2) ----------------
    tc_gemm<0,0><<<dim3(D_/128, BS_/128, 1), 128, GSM>>>(D_,
        at2, D_, 0,  w2e, D_, 0,  tmp, D_, 0,  b2, 1.0f);
    ln_k<1><<<BS_, 256>>>(y, tmp, l2g, l2b, a2);

    // ---------------- FFN ----------------
    tc_gemm<0,1><<<dim3(DF_/128, BS_/128, 1), 128, GSM>>>(D_,
        a2, D_, 0,  wf1t, D_, 0,  ffh, DF_, 0,  bf1, 1.0f);
    tc_gemm<0,0><<<dim3(D_/128, BS_/128, 1), 128, GSM>>>(DF_,
        ffh, DF_, 0,  wf2t, DF_, 0,  tmp, D_, 0,  bf2, 1.0f);
    ln_k<0><<<BS_, 256>>>(y, tmp, l3g, l3b, out);
}

// round 16
// speedup vs baseline: 7.0545x; 1.4137x over previous
#include <cuda_runtime.h>
#include <cuda_fp16.h>
#include <cstdint>
#include <math.h>

// ---------------------------------------------------------------------------
// DecoderLayer: B=2, S=2048, D=1024, H=16, DF=4096, DK=64
// Round 13 (= Round 12 resubmit; prior bench died to container infra):
// all GEMMs + flash on mma.sync.m16n8k16.f32.f16.f16.f32.
// fp16 inputs (same 10-bit mantissa as tf32), fp32 accumulate; scores and
// LN inputs stay fp32. BK=64 halves = same 128B SW128 rows as before.
// ---------------------------------------------------------------------------

#define B_  2
#define S_  2048
#define D_  1024
#define H_  16
#define DF_ 4096
#define DK_ 64
#define BS_ (B_*S_)
#define QK2 2048
#define SCALE_ 0.125f
#define EPS_   1e-5f

// -------------------------- scratch (static device) -------------------------
__device__ __half g_yh [(size_t)BS_*D_];     // y  fp16 (GEMM A)
__device__ __half g_xh [(size_t)BS_*D_];     // x  fp16 (cross-sc B)
__device__ __half g_xt [(size_t)B_*D_*S_];   // x^T fp16 (attn2 B)
__device__ __half g_qk [(size_t)B_*S_*QK2];  // [b][s][q|k] fp16
__device__ __half g_vt [(size_t)B_*D_*S_];   // v^T fp16
__device__ float  g_sc [(size_t)B_*S_*S_];   // cross scores fp32
__device__ __half g_ph [(size_t)B_*S_*S_];   // cross P fp16
__device__ __half g_cat[(size_t)BS_*D_];
__device__ float  g_tmp[(size_t)BS_*D_];
__device__ __half g_a1 [(size_t)BS_*D_];
__device__ __half g_at2[(size_t)BS_*D_];
__device__ __half g_a2 [(size_t)BS_*D_];
__device__ __half g_ffh[(size_t)BS_*DF_];
__device__ __half g_wqkt[(size_t)2*D_*D_];
__device__ float  g_bqk [QK2];
__device__ __half g_wvt[(size_t)D_*D_];
__device__ __half g_w1t[(size_t)D_*D_];
__device__ __half g_w2e[(size_t)D_*D_];
__device__ __half g_wf1t[(size_t)DF_*D_];
__device__ __half g_wf2t[(size_t)D_*DF_];

// ------------------------------ PTX helpers ---------------------------------
__device__ __forceinline__ uint32_t smem_u32(const void* p) {
    uint32_t a;
    asm("{ .reg .u64 t; cvta.to.shared.u64 t, %1; cvt.u32.u64 %0, t; }"
        : "=r"(a) : "l"(p));
    return a;
}
#define CP16(dst, src) \
    asm volatile("cp.async.cg.shared.global [%0], [%1], 16;" \
                 :: "r"(dst), "l"(src))
#define CP_COMMIT() asm volatile("cp.async.commit_group;" ::: "memory")
#define CP_WAIT0()  asm volatile("cp.async.wait_group 0;" ::: "memory")
#define CP_WAIT1()  asm volatile("cp.async.wait_group 1;" ::: "memory")
#define LDSM4(r0,r1,r2,r3,addr) \
    asm volatile("ldmatrix.sync.aligned.m8n8.x4.shared.b16 {%0,%1,%2,%3}, [%4];" \
                 : "=r"(r0),"=r"(r1),"=r"(r2),"=r"(r3) : "r"(addr))
#define MMA16(d, a0,a1,a2,a3, b0,b1) \
    asm volatile("mma.sync.aligned.m16n8k16.row.col.f32.f16.f16.f32 " \
                 "{%0,%1,%2,%3},{%4,%5,%6,%7},{%8,%9},{%0,%1,%2,%3};" \
                 : "+f"(d[0]),"+f"(d[1]),"+f"(d[2]),"+f"(d[3]) \
                 : "r"(a0),"r"(a1),"r"(a2),"r"(a3),"r"(b0),"r"(b1))

// ------------------------------- fp16 GEMM -----------------------------------
// C[z] = alpha * A[z] @ B[z]^T (+bias)(,relu).  BM=BN=128, BK=64 halves.
// 4 warps (64x64 tiles), 3-stage cp.async, stage issued before compute.
// OUTH: 1 = fp16 C, 0 = fp32 C.  TRC: transposed store.
template<int TRC,int RELU,int OUTH>
__global__ __launch_bounds__(128,2)
void hgemm(int K,
           const __half* __restrict__ A,  int lda, long long sA,
           const __half* __restrict__ Bg, int ldb, long long sB,
           void* __restrict__ Cv,         int ldc, long long sC,
           const float* __restrict__ bias, float alpha)
{
    constexpr int STAGE = 32768;
    constexpr int OFF_B = 16384;

    const int m0 = blockIdx.y * 128;
    const int n0 = blockIdx.x * 128;
    extern __shared__ __align__(1024) char smem[];
    const uint32_t sbase = smem_u32(smem);
    const int tid = threadIdx.x, wid = tid >> 5, lane = tid & 31;

    const long long z = blockIdx.z;
    A  += z * sA;
    Bg += z * sB;

    const int T = K >> 6;

    auto stage = [&](int s, int k0) {
        const __half* Ab = A + (size_t)m0 * lda + k0;
        const uint32_t sa = sbase + s * STAGE;
        #pragma unroll
        for (int it = 0; it < 8; it++) {
            int idx = tid + (it << 7);
            int row = idx >> 3, c16 = idx & 7;
            uint32_t off = ((uint32_t)row << 7) + ((uint32_t)c16 << 4);
            off ^= (off >> 3) & 0x70;
            CP16(sa + off, Ab + (size_t)row * lda + (c16 << 3));
        }
        const __half* Bb = Bg + (size_t)n0 * ldb + k0;
        const uint32_t sb = sbase + s * STAGE + OFF_B;
        #pragma unroll
        for (int it = 0; it < 8; it++) {
            int idx = tid + (it << 7);
            int row = idx >> 3, c16 = idx & 7;
            uint32_t off = ((uint32_t)row << 7) + ((uint32_t)c16 << 4);
            off ^= (off >> 3) & 0x70;
            CP16(sb + off, Bb + (size_t)row * ldb + (c16 << 3));
        }
    };

    const int mw = wid & 1, nw = wid >> 1;
    const int mbase = mw * 64, nbase = nw * 64;
    const int swz = lane & 7;
    const int ca  = lane >> 4;          // k-half selector for 16-row ldmatrix
    uint32_t aoffb[4], boffb[4];
    {
        int ar0 = mbase + (lane & 15);
        #pragma unroll
        for (int mt = 0; mt < 4; mt++) aoffb[mt] = (uint32_t)(ar0 + mt * 16) << 7;
        int br0 = nbase + (lane & 15);
        #pragma unroll
        for (int p = 0; p < 4; p++) boffb[p] = (uint32_t)(br0 + p * 16) << 7;
    }

    float acc[4][8][4];
    #pragma unroll
    for (int mt = 0; mt < 4; mt++)
        #pragma unroll
        for (int nt = 0; nt < 8; nt++)
            #pragma unroll
            for (int j = 0; j < 4; j++) acc[mt][nt][j] = 0.0f;

    stage(0, 0);
    CP_COMMIT();
    if (T > 1) { stage(1, 64); CP_COMMIT(); }

    int buf = 0;
    for (int t = 0; t < T; t++) {
        if (t + 1 < T) CP_WAIT1(); else CP_WAIT0();
        __syncthreads();
        if (t + 2 < T) {               // buffer (t+2)%3 freed by compute(t-1)
            int sb = buf + 2; if (sb >= 3) sb -= 3;
            stage(sb, (t + 2) << 6);
            CP_COMMIT();
        }
        const uint32_t aB = sbase + buf * STAGE;
        const uint32_t bB = aB + OFF_B;
        #pragma unroll
        for (int kc = 0; kc < 4; kc++) {
            const uint32_t sw = (uint32_t)(((2 * kc + ca) ^ swz) << 4);
            uint32_t af[4][4], bf[4][4];
            #pragma unroll
            for (int mt = 0; mt < 4; mt++)
                LDSM4(af[mt][0], af[mt][1], af[mt][2], af[mt][3],
                      aB + aoffb[mt] + sw);
            #pragma unroll
            for (int p = 0; p < 4; p++)
                LDSM4(bf[p][0], bf[p][1], bf[p][2], bf[p][3],
                      bB + boffb[p] + sw);
            #pragma unroll
            for (int mt = 0; mt < 4; mt++)
                #pragma unroll
                for (int p = 0; p < 4; p++) {
                    MMA16(acc[mt][2 * p],     af[mt][0], af[mt][1], af[mt][2], af[mt][3],
                          bf[p][0], bf[p][2]);
                    MMA16(acc[mt][2 * p + 1], af[mt][0], af[mt][1], af[mt][2], af[mt][3],
                          bf[p][1], bf[p][3]);
                }
        }
        if (++buf == 3) buf = 0;
    }

    // epilogue
    const int g = lane >> 2, tg = lane & 3;
    #pragma unroll
    for (int mt = 0; mt < 4; mt++) {
        const int r0 = m0 + mbase + mt * 16 + g;
        #pragma unroll
        for (int nt = 0; nt < 8; nt++) {
            const int col = n0 + nbase + nt * 8 + tg * 2;
            float v0 = acc[mt][nt][0] * alpha, v1 = acc[mt][nt][1] * alpha;
            float v2 = acc[mt][nt][2] * alpha, v3 = acc[mt][nt][3] * alpha;
            if (bias) {
                float b0 = bias[col], b1 = bias[col + 1];
                v0 += b0; v1 += b1; v2 += b0; v3 += b1;
            }
            if (RELU) {
                v0 = fmaxf(v0, 0.f); v1 = fmaxf(v1, 0.f);
                v2 = fmaxf(v2, 0.f); v3 = fmaxf(v3, 0.f);
            }
            if (OUTH) {
                __half* C = (__half*)Cv + z * sC;
                if (!TRC) {
                    *(__half2*)(C + (size_t)r0 * ldc + col)       = __floats2half2_rn(v0, v1);
                    *(__half2*)(C + (size_t)(r0 + 8) * ldc + col) = __floats2half2_rn(v2, v3);
                } else {
                    C[(size_t)col       * ldc + r0]     = __float2half_rn(v0);
                    C[(size_t)(col + 1) * ldc + r0]     = __float2half_rn(v1);
                    C[(size_t)col       * ldc + r0 + 8] = __float2half_rn(v2);
                    C[(size_t)(col + 1) * ldc + r0 + 8] = __float2half_rn(v3);
                }
            } else {
                float* C = (float*)Cv + z * sC;
                *(float2*)(C + (size_t)r0 * ldc + col)       = make_float2(v0, v1);
                *(float2*)(C + (size_t)(r0 + 8) * ldc + col) = make_float2(v2, v3);
            }
        }
    }
}

// --------------------------- flash self-attention (fp16) ---------------------
__global__ __launch_bounds__(256)
void flash_k(const __half* __restrict__ qkg, const __half* __restrict__ vtg,
             __half* __restrict__ catg)
{
    constexpr int OFF_Q = 0;                  // [128][64h] = 16KB
    constexpr int OFF_K = 16384;              // 2 bufs x 16KB
    constexpr int OFF_V = 49152;              // 2 bufs x 16KB (2 chunks x 8KB)
    constexpr int OFF_P = 81920;              // 2 chunks x 16KB = 32KB
    constexpr int OFF_PM = 114688;
    constexpr int OFF_PL = 115712;

    const int qb = (int)gridDim.x - 1 - (int)blockIdx.x;
    const int h = blockIdx.y, b = blockIdx.z;
    extern __shared__ __align__(1024) char smem[];
    const uint32_t sbase = smem_u32(smem);
    const int tid = threadIdx.x, wid = tid >> 5, lane = tid & 31;
    const int mw = wid & 3, nw = wid >> 2;
    const int mbase = mw * 32;
    const int nbS = nw * 64;
    const int nbV = nw * 32;
    const int g = lane >> 2, tg = lane & 3;
    const int swz = lane & 7;
    const int ca  = lane >> 4;

    const size_t SQ = (size_t)S_ * QK2;
    const __half* Qs = qkg + (size_t)b * SQ + (size_t)(qb * 128) * QK2 + h * 64;
    const __half* Ks = qkg + (size_t)b * SQ + 1024 + h * 64;
    const __half* Vs = vtg + (size_t)b * ((size_t)D_ * S_) + (size_t)(h * 64) * S_;

    uint32_t aoffb[2], boffS[4], boffV[2];
    {
        int ar0 = mbase + (lane & 15);
        aoffb[0] = (uint32_t)ar0 << 7;
        aoffb[1] = (uint32_t)(ar0 + 16) << 7;
        int br0 = nbS + (lane & 15);
        #pragma unroll
        for (int p = 0; p < 4; p++) boffS[p] = (uint32_t)(br0 + p * 16) << 7;
        int bv0 = nbV + (lane & 15);
        boffV[0] = (uint32_t)bv0 << 7;
        boffV[1] = (uint32_t)(bv0 + 16) << 7;
    }

    auto stageKV = [&](int bufd, int kb) {
        const uint32_t kB = sbase + OFF_K + bufd * 16384;
        #pragma unroll
        for (int it = 0; it < 4; it++) {
            int idx = tid + (it << 8);
            int row = idx >> 3, c16 = idx & 7;
            uint32_t off = ((uint32_t)row << 7) + ((uint32_t)c16 << 4);
            off ^= (off >> 3) & 0x70;
            CP16(kB + off, Ks + (size_t)(kb * 128 + row) * QK2 + (c16 << 3));
        }
        const uint32_t vB = sbase + OFF_V + bufd * 16384;
        #pragma unroll
        for (int it = 0; it < 4; it++) {
            int idx = tid + (it << 8);
            int chunk = idx >> 9, rem = idx & 511;
            int row = rem >> 3, c16 = rem & 7;
            uint32_t off = ((uint32_t)row << 7) + ((uint32_t)c16 << 4);
            off ^= (off >> 3) & 0x70;
            CP16(vB + chunk * 8192 + off,
                 Vs + (size_t)row * S_ + kb * 128 + chunk * 64 + (c16 << 3));
        }
    };

    // Q resident + first K/V
    #pragma unroll
    for (int it = 0; it < 4; it++) {
        int idx = tid + (it << 8);
        int row = idx >> 3, c16 = idx & 7;
        uint32_t off = ((uint32_t)row << 7) + ((uint32_t)c16 << 4);
        off ^= (off >> 3) & 0x70;
        CP16(sbase + OFF_Q + off, Qs + (size_t)row * QK2 + (c16 << 3));
    }
    stageKV(0, 0);
    CP_COMMIT();

    float oacc[2][4][4];
    #pragma unroll
    for (int mt = 0; mt < 2; mt++)
        #pragma unroll
        for (int nt = 0; nt < 4; nt++)
            #pragma unroll
            for (int j = 0; j < 4; j++) oacc[mt][nt][j] = 0.0f;
    float m_run[2][2] = {{-1e30f, -1e30f}, {-1e30f, -1e30f}};
    float l_run[2][2] = {{0.f, 0.f}, {0.f, 0.f}};
    float* pm = (float*)(smem + OFF_PM);
    float* pl = (float*)(smem + OFF_PL);

    for (int kb = 0; kb <= qb; kb++) {
        const int bufc = kb & 1;
        CP_WAIT0();
        __syncthreads();
        if (kb < qb) { stageKV(bufc ^ 1, kb + 1); CP_COMMIT(); }

        // ---- S = Q @ K^T (warp 32x64, k=64) ----
        float sacc[2][8][4];
        #pragma unroll
        for (int mt = 0; mt < 2; mt++)
            #pragma unroll
            for (int nt = 0; nt < 8; nt++)
                #pragma unroll
                for (int j = 0; j < 4; j++) sacc[mt][nt][j] = 0.0f;
        {
            const uint32_t aB = sbase + OFF_Q;
            const uint32_t bB = sbase + OFF_K + bufc * 16384;
            #pragma unroll
            for (int kc = 0; kc < 4; kc++) {
                const uint32_t sw = (uint32_t)(((2 * kc + ca) ^ swz) << 4);
                uint32_t af[2][4], bf[4][4];
                #pragma unroll
                for (int mt = 0; mt < 2; mt++)
                    LDSM4(af[mt][0], af[mt][1], af[mt][2], af[mt][3],
                          aB + aoffb[mt] + sw);
                #pragma unroll
                for (int p = 0; p < 4; p++)
                    LDSM4(bf[p][0], bf[p][1], bf[p][2], bf[p][3],
                          bB + boffS[p] + sw);
                #pragma unroll
                for (int mt = 0; mt < 2; mt++)
                    #pragma unroll
                    for (int p = 0; p < 4; p++) {
                        MMA16(sacc[mt][2 * p],     af[mt][0], af[mt][1], af[mt][2], af[mt][3],
                              bf[p][0], bf[p][2]);
                        MMA16(sacc[mt][2 * p + 1], af[mt][0], af[mt][1], af[mt][2], af[mt][3],
                              bf[p][1], bf[p][3]);
                    }
            }
        }

        // ---- scale + causal mask + row max ----
        const bool diag = (kb == qb);
        float tmx[2][2] = {{-1e30f, -1e30f}, {-1e30f, -1e30f}};
        #pragma unroll
        for (int mt = 0; mt < 2; mt++)
            #pragma unroll
            for (int nt = 0; nt < 8; nt++)
                #pragma unroll
                for (int j = 0; j < 4; j++) {
                    float v = sacc[mt][nt][j] * SCALE_;
                    if (diag) {
                        int cl = nbS + nt * 8 + tg * 2 + (j & 1);
                        int rl = mbase + mt * 16 + g + ((j & 2) << 2);
                        if (cl > rl) v = -1e30f;
                    }
                    sacc[mt][nt][j] = v;
                    tmx[mt][j >> 1] = fmaxf(tmx[mt][j >> 1], v);
                }
        #pragma unroll
        for (int mt = 0; mt < 2; mt++)
            #pragma unroll
            for (int hh = 0; hh < 2; hh++) {
                float t = tmx[mt][hh];
                t = fmaxf(t, __shfl_xor_sync(0xffffffffu, t, 1));
                t = fmaxf(t, __shfl_xor_sync(0xffffffffu, t, 2));
                if (tg == 0)
                    pm[nw * 128 + mbase + mt * 16 + hh * 8 + g] = t;
            }
        __syncthreads();

        float cf[2][2], mnew[2][2];
        #pragma unroll
        for (int mt = 0; mt < 2; mt++)
            #pragma unroll
            for (int hh = 0; hh < 2; hh++) {
                int r = mbase + mt * 16 + hh * 8 + g;
                float tm = fmaxf(pm[r], pm[128 + r]);
                float mn = fmaxf(m_run[mt][hh], tm);
                cf[mt][hh] = __expf(m_run[mt][hh] - mn);
                m_run[mt][hh] = mn;
                mnew[mt][hh] = mn;
            }

        // ---- exp + P store (fp16) + partial sums ----
        float ts[2][2] = {{0.f, 0.f}, {0.f, 0.f}};
        #pragma unroll
        for (int mt = 0; mt < 2; mt++) {
            const int r0 = mbase + mt * 16 + g;
            #pragma unroll
            for (int nt = 0; nt < 8; nt++) {
                const int col = nbS + nt * 8 + tg * 2;
                float p0 = __expf(sacc[mt][nt][0] - mnew[mt][0]);
                float p1 = __expf(sacc[mt][nt][1] - mnew[mt][0]);
                float p2 = __expf(sacc[mt][nt][2] - mnew[mt][1]);
                float p3 = __expf(sacc[mt][nt][3] - mnew[mt][1]);
                ts[mt][0] += p0 + p1;
                ts[mt][1] += p2 + p3;
                uint32_t base = (uint32_t)(col >> 6) * 16384 + ((uint32_t)(col & 63) << 1);
                uint32_t off0 = base + ((uint32_t)r0 << 7);
                off0 ^= (off0 >> 3) & 0x70;
                *(__half2*)(smem + OFF_P + off0) = __floats2half2_rn(p0, p1);
                uint32_t off1 = base + ((uint32_t)(r0 + 8) << 7);
                off1 ^= (off1 >> 3) & 0x70;
                *(__half2*)(smem + OFF_P + off1) = __floats2half2_rn(p2, p3);
            }
        }
        #pragma unroll
        for (int mt = 0; mt < 2; mt++)
            #pragma unroll
            for (int hh = 0; hh < 2; hh++) {
                float t = ts[mt][hh];
                t += __shfl_xor_sync(0xffffffffu, t, 1);
                t += __shfl_xor_sync(0xffffffffu, t, 2);
                if (tg == 0)
                    pl[nw * 128 + mbase + mt * 16 + hh * 8 + g] = t;
            }
        __syncthreads();

        #pragma unroll
        for (int mt = 0; mt < 2; mt++)
            #pragma unroll
            for (int hh = 0; hh < 2; hh++) {
                int r = mbase + mt * 16 + hh * 8 + g;
                l_run[mt][hh] = l_run[mt][hh] * cf[mt][hh] + pl[r] + pl[128 + r];
            }
        #pragma unroll
        for (int mt = 0; mt < 2; mt++)
            #pragma unroll
            for (int nt = 0; nt < 4; nt++)
                #pragma unroll
                for (int j = 0; j < 4; j++)
                    oacc[mt][nt][j] *= cf[mt][j >> 1];

        // ---- O += P @ V (warp 32x32, k=128) ----
        #pragma unroll
        for (int kc = 0; kc < 8; kc++) {
            const uint32_t c16u = (uint32_t)(2 * kc + ca);
            const uint32_t sw = (((c16u & 7) ^ (uint32_t)swz) << 4);
            const uint32_t aB = sbase + OFF_P + ((c16u >> 3) << 14);
            const uint32_t bB = sbase + OFF_V + bufc * 16384 + ((c16u >> 3) << 13);
            uint32_t af[2][4], bf[2][4];
            #pragma unroll
            for (int mt = 0; mt < 2; mt++)
                LDSM4(af[mt][0], af[mt][1], af[mt][2], af[mt][3],
                      aB + aoffb[mt] + sw);
            #pragma unroll
            for (int p = 0; p < 2; p++)
                LDSM4(bf[p][0], bf[p][1], bf[p][2], bf[p][3],
                      bB + boffV[p] + sw);
            #pragma unroll
            for (int mt = 0; mt < 2; mt++)
                #pragma unroll
                for (int p = 0; p < 2; p++) {
                    MMA16(oacc[mt][2 * p],     af[mt][0], af[mt][1], af[mt][2], af[mt][3],
                          bf[p][0], bf[p][2]);
                    MMA16(oacc[mt][2 * p + 1], af[mt][0], af[mt][1], af[mt][2], af[mt][3],
                          bf[p][1], bf[p][3]);
                }
        }
        __syncthreads();   // protect P / pm / pl before next tile
    }

    // ---- epilogue: O / l -> cat fp16 ----
    __half* dst = catg + (size_t)b * ((size_t)S_ * D_) + (size_t)(qb * 128) * D_ + h * 64;
    #pragma unroll
    for (int mt = 0; mt < 2; mt++) {
        const int r0 = mbase + mt * 16 + g;
        const float i0 = 1.0f / l_run[mt][0];
        const float i1 = 1.0f / l_run[mt][1];
        #pragma unroll
        for (int nt = 0; nt < 4; nt++) {
            const int col = nbV + nt * 8 + tg * 2;
            *(__half2*)(dst + (size_t)r0 * D_ + col) =
                __floats2half2_rn(oacc[mt][nt][0] * i0, oacc[mt][nt][1] * i0);
            *(__half2*)(dst + (size_t)(r0 + 8) * D_ + col) =
                __floats2half2_rn(oacc[mt][nt][2] * i1, oacc[mt][nt][3] * i1);
        }
    }
}

// ------------------------------ softmax (cross) ------------------------------
__global__ __launch_bounds__(256)
void softmax_k(const float* __restrict__ sc, __half* __restrict__ ph)
{
    __shared__ float buf[S_];
    __shared__ float red[256];
    const int row = blockIdx.x;
    const int tid = threadIdx.x;
    const float* p = sc + (size_t)row * S_;
    __half* o = ph + (size_t)row * S_;

    float mx = -3.0e38f;
    for (int t = tid; t < S_; t += 256) {
        float vv = p[t];
        buf[t] = vv;
        mx = fmaxf(mx, vv);
    }
    red[tid] = mx;
    __syncthreads();
    for (int o2 = 128; o2 > 0; o2 >>= 1) {
        if (tid < o2) red[tid] = fmaxf(red[tid], red[tid + o2]);
        __syncthreads();
    }
    mx = red[0];
    __syncthreads();

    float sum = 0.0f;
    for (int t = tid; t < S_; t += 256) {
        float e = __expf(buf[t] - mx);
        buf[t] = e;
        sum += e;
    }
    red[tid] = sum;
    __syncthreads();
    for (int o2 = 128; o2 > 0; o2 >>= 1) {
        if (tid < o2) red[tid] += red[tid + o2];
        __syncthreads();
    }
    const float inv = 1.0f / red[0];

    for (int t = tid; t < S_; t += 256)
        o[t] = __float2half_rn(buf[t] * inv);
}

// ------------------------- residual + LayerNorm ------------------------------
// OUTH=1: write fp16 (feeds GEMM); OUTH=0: write fp32 (final output)
template<int OUTH>
__global__ __launch_bounds__(256)
void ln_k(const float* __restrict__ y, const float* __restrict__ t,
          const float* __restrict__ g, const float* __restrict__ bb,
          void* __restrict__ outv)
{
    const int row = blockIdx.x;
    const int tid = threadIdx.x;
    const float* yr = y + (size_t)row * D_;
    const float* tr = t + (size_t)row * D_;

    float vloc[4];
    float s = 0.0f, s2 = 0.0f;
    #pragma unroll
    for (int i = 0; i < 4; i++) {
        int c = tid + i * 256;
        float vv = yr[c] + tr[c];
        vloc[i] = vv;
        s  += vv;
        s2 += vv * vv;
    }
    __shared__ float rs[256], rq[256];
    rs[tid] = s; rq[tid] = s2;
    __syncthreads();
    for (int o = 128; o > 0; o >>= 1) {
        if (tid < o) { rs[tid] += rs[tid + o]; rq[tid] += rq[tid + o]; }
        __syncthreads();
    }
    const float mean = rs[0] * (1.0f / D_);
    const float var  = rq[0] * (1.0f / D_) - mean * mean;
    const float inv  = rsqrtf(var + EPS_);

    #pragma unroll
    for (int i = 0; i < 4; i++) {
        int c = tid + i * 256;
        float o = (vloc[i] - mean) * inv * g[c] + bb[c];
        if (OUTH) ((__half*)outv)[(size_t)row * D_ + c] = __float2half_rn(o);
        else      ((float*)outv)[(size_t)row * D_ + c] = o;
    }
}

// ------------------------------ prep kernels ---------------------------------
__global__ __launch_bounds__(256)
void k_h(const float* __restrict__ in, __half* __restrict__ out)
{
    int i = blockIdx.x * 256 + threadIdx.x;
    float2 v = ((const float2*)in)[i];
    ((__half2*)out)[i] = __floats2half2_rn(v.x, v.y);
}

__global__ __launch_bounds__(256)
void k_trh(const float* __restrict__ in, __half* __restrict__ out,
           int R, int C, long long si, long long so)
{
    __shared__ float t[32][33];
    in  += (size_t)blockIdx.z * si;
    out += (size_t)blockIdx.z * so;
    const int r0 = blockIdx.y * 32, c0 = blockIdx.x * 32;
    const int tx = threadIdx.x & 31, ty = threadIdx.x >> 5;
    #pragma unroll
    for (int j = 0; j < 4; j++)
        t[ty + j * 8][tx] = in[(size_t)(r0 + ty + j * 8) * C + c0 + tx];
    __syncthreads();
    #pragma unroll
    for (int j = 0; j < 4; j++)
        out[(size_t)(c0 + ty + j * 8) * R + r0 + tx] = __float2half_rn(t[tx][ty + j * 8]);
}

__global__ __launch_bounds__(256)
void k_w2eff(const float* __restrict__ W2, __half* __restrict__ o)
{
    __shared__ float t[32][33];
    const int d0 = blockIdx.y * 32, c0 = blockIdx.x * 32;
    const int tx = threadIdx.x & 31, ty = threadIdx.x >> 5;
    float r[4] = {0.f, 0.f, 0.f, 0.f};
    for (int h = 0; h < H_; h++) {
        #pragma unroll
        for (int j = 0; j < 4; j++)
            r[j] += W2[(size_t)(h * D_ + d0 + ty + j * 8) * D_ + c0 + tx];
    }
    #pragma unroll
    for (int j = 0; j < 4; j++) t[ty + j * 8][tx] = r[j];
    __syncthreads();
    #pragma unroll
    for (int j = 0; j < 4; j++)
        o[(size_t)(c0 + ty + j * 8) * D_ + d0 + tx] = __float2half_rn(t[tx][ty + j * 8]);
}

__global__ __launch_bounds__(256)
void k_bcat(const float* __restrict__ bq, const float* __restrict__ bk,
            float* __restrict__ o)
{
    int i = blockIdx.x * 256 + threadIdx.x;
    o[i] = (i < 1024) ? bq[i] : bk[i - 1024];
}

// ------------------------------ launcher -------------------------------------
extern "C" void kernel_launch(void* const* d_in, const int* in_sizes, int n_in,
                              void* d_out, int out_size)
{
    const float* x   = (const float*)d_in[0];
    const float* y   = (const float*)d_in[1];
    // d_in[2] = y_mask (causal tril) — analytic
    const float* Wq  = (const float*)d_in[3];
    const float* bq  = (const float*)d_in[4];
    const float* Wk  = (const float*)d_in[5];
    const float* bk  = (const float*)d_in[6];
    const float* Wv  = (const float*)d_in[7];
    const float* bv  = (const float*)d_in[8];
    const float* W1  = (const float*)d_in[9];
    const float* b1  = (const float*)d_in[10];
    const float* l1g = (const float*)d_in[11];
    const float* l1b = (const float*)d_in[12];
    const float* W2  = (const float*)d_in[13];
    const float* b2  = (const float*)d_in[14];
    const float* l2g = (const float*)d_in[15];
    const float* l2b = (const float*)d_in[16];
    const float* Wf1 = (const float*)d_in[17];
    const float* bf1 = (const float*)d_in[18];
    const float* Wf2 = (const float*)d_in[19];
    const float* bf2 = (const float*)d_in[20];
    const float* l3g = (const float*)d_in[21];
    const float* l3b = (const float*)d_in[22];
    float* out = (float*)d_out;

    __half *yh, *xh, *xt, *qk, *vt, *ph, *cat, *a1, *at2, *a2, *ffh;
    __half *wqkt, *wvt, *w1t, *w2e, *wf1t, *wf2t;
    float *sc, *tmp, *bqk;
    cudaGetSymbolAddress((void**)&yh,   g_yh);
    cudaGetSymbolAddress((void**)&xh,   g_xh);
    cudaGetSymbolAddress((void**)&xt,   g_xt);
    cudaGetSymbolAddress((void**)&qk,   g_qk);
    cudaGetSymbolAddress((void**)&vt,   g_vt);
    cudaGetSymbolAddress((void**)&sc,   g_sc);
    cudaGetSymbolAddress((void**)&ph,   g_ph);
    cudaGetSymbolAddress((void**)&cat,  g_cat);
    cudaGetSymbolAddress((void**)&tmp,  g_tmp);
    cudaGetSymbolAddress((void**)&a1,   g_a1);
    cudaGetSymbolAddress((void**)&at2,  g_at2);
    cudaGetSymbolAddress((void**)&a2,   g_a2);
    cudaGetSymbolAddress((void**)&ffh,  g_ffh);
    cudaGetSymbolAddress((void**)&wqkt, g_wqkt);
    cudaGetSymbolAddress((void**)&bqk,  g_bqk);
    cudaGetSymbolAddress((void**)&wvt,  g_wvt);
    cudaGetSymbolAddress((void**)&w1t,  g_w1t);
    cudaGetSymbolAddress((void**)&w2e,  g_w2e);
    cudaGetSymbolAddress((void**)&wf1t, g_wf1t);
    cudaGetSymbolAddress((void**)&wf2t, g_wf2t);

    const int GSM = 3 * 32768;
    const int FSM = 116736;
    cudaFuncSetAttribute(hgemm<0,0,1>, cudaFuncAttributeMaxDynamicSharedMemorySize, GSM);
    cudaFuncSetAttribute(hgemm<1,0,1>, cudaFuncAttributeMaxDynamicSharedMemorySize, GSM);
    cudaFuncSetAttribute(hgemm<0,0,0>, cudaFuncAttributeMaxDynamicSharedMemorySize, GSM);
    cudaFuncSetAttribute(hgemm<0,1,1>, cudaFuncAttributeMaxDynamicSharedMemorySize, GSM);
    cudaFuncSetAttribute(flash_k, cudaFuncAttributeMaxDynamicSharedMemorySize, FSM);

    const long long SD  = (long long)S_ * D_;
    const long long SS  = (long long)S_ * S_;
    const long long DS  = (long long)D_ * S_;
    const long long SQK = (long long)S_ * QK2;

    // ---------------- prep ----------------
    k_h<<<(BS_ * D_) / 512, 256>>>(y, yh);
    k_h<<<(BS_ * D_) / 512, 256>>>(x, xh);
    k_trh<<<dim3(D_/32, S_/32, B_),  256>>>(x,  xt,  S_,  D_,  SD, DS);
    k_trh<<<dim3(DK_/32, D_/32, H_), 256>>>(Wq, wqkt,                 D_, DK_, (long long)D_*DK_, (long long)DK_*D_);
    k_trh<<<dim3(DK_/32, D_/32, H_), 256>>>(Wk, wqkt + (size_t)D_*D_, D_, DK_, (long long)D_*DK_, (long long)DK_*D_);
    k_trh<<<dim3(DK_/32, D_/32, H_), 256>>>(Wv, wvt, D_,  DK_, (long long)D_*DK_, (long long)DK_*D_);
    k_trh<<<dim3(D_/32, D_/32, 1),   256>>>(W1, w1t, D_,  D_,  0, 0);
    k_trh<<<dim3(DF_/32, D_/32, 1),  256>>>(Wf1, wf1t, D_, DF_, 0, 0);
    k_trh<<<dim3(D_/32, DF_/32, 1),  256>>>(Wf2, wf2t, DF_, D_, 0, 0);
    k_w2eff<<<dim3(D_/32, D_/32, 1), 256>>>(W2, w2e);
    k_bcat<<<QK2 / 256, 256>>>(bq, bk, bqk);

    // ---------------- Q+K merged projection (N=2048) ----------------
    hgemm<0,0,1><<<dim3(QK2/128, S_/128, B_), 128, GSM>>>(D_,
        yh, D_, SD,  wqkt, D_, 0,  qk, QK2, SQK,  bqk, 1.0f);

    // ---------------- V projection (transposed fp16 output) ----------------
    hgemm<1,0,1><<<dim3(D_/128, S_/128, B_), 128, GSM>>>(D_,
        yh, D_, SD,  wvt, D_, 0,  vt, S_, DS,  bv, 1.0f);

    // ---------------- fused self-attention ----------------
    flash_k<<<dim3(S_ / 128, H_, B_), 256, FSM>>>(qk, vt, cat);

    // ---------------- a1 = LN(y + cat @ W1 + b1) ----------------
    hgemm<0,0,0><<<dim3(D_/128, BS_/128, 1), 128, GSM>>>(D_,
        cat, D_, 0,  w1t, D_, 0,  tmp, D_, 0,  b1, 1.0f);
    ln_k<1><<<BS_, 256>>>(y, tmp, l1g, l1b, a1);

    // ---------------- cross scores (fp32 out) + softmax (P fp16) -------------
    hgemm<0,0,0><<<dim3(S_/128, S_/128, B_), 128, GSM>>>(D_,
        a1, D_, SD,  xh, D_, SD,  sc, S_, SS,  nullptr, SCALE_);
    softmax_k<<<B_ * S_, 256>>>(sc, ph);

    // ---------------- attn2 = P @ x ----------------
    hgemm<0,0,1><<<dim3(D_/128, S_/128, B_), 128, GSM>>>(S_,
        ph, S_, SS,  xt, S_, DS,  at2, D_, SD,  nullptr, 1.0f);

    // ---------------- a2 = LN(y + attn2 @ W2_eff + b2) ----------------
    hgemm<0,0,0><<<dim3(D_/128, BS_/128, 1), 128, GSM>>>(D_,
        at2, D_, 0,  w2e, D_, 0,  tmp, D_, 0,  b2, 1.0f);
    ln_k<1><<<BS_, 256>>>(y, tmp, l2g, l2b, a2);

    // ---------------- FFN ----------------
    hgemm<0,1,1><<<dim3(DF_/128, BS_/128, 1), 128, GSM>>>(D_,
        a2, D_, 0,  wf1t, D_, 0,  ffh, DF_, 0,  bf1, 1.0f);
    hgemm<0,0,0><<<dim3(D_/128, BS_/128, 1), 128, GSM>>>(DF_,
        ffh, DF_, 0,  wf2t, DF_, 0,  tmp, D_, 0,  bf2, 1.0f);
    ln_k<0><<<BS_, 256>>>(y, tmp, l3g, l3b, out);
}